// round 7
// baseline (speedup 1.0000x reference)
#include <cuda_runtime.h>
#include <math.h>

#define NF   512
#define TK   196
#define EM   2560
#define HID  512
#define E4   (EM/4)
#define POOL_T 320
#define NTOP 64
#define KS_H 9
#define KS_F 8

// ---------------- scratch (static device globals) ----------------------------
__device__ float g_pooled[NF * EM];         // layer-normed pooled features
__device__ float g_invn[NF];                // 1/||pooled_ln|| per frame
__device__ float g_tproj[HID];              // txt_ln @ W1_top + b1
__device__ float g_hp[KS_H * NF * HID];     // split-K partials of pooled_ln @ W1_bot
__device__ float g_fp[KS_F * NTOP * NF];    // split-K partials of top-64 f2f rows
__device__ float g_gates[NF];
__device__ int   g_order[NF];
__device__ unsigned int g_mask[NTOP * 16];  // f2f>0.98 bitmask for top-64 rows

// ---------------- block reduce of two scalars --------------------------------
__device__ __forceinline__ void blk_reduce2(float& a, float& b, float* sm, int nwarp) {
    int lane = threadIdx.x & 31, wid = threadIdx.x >> 5;
#pragma unroll
    for (int o = 16; o > 0; o >>= 1) {
        a += __shfl_down_sync(0xffffffffu, a, o);
        b += __shfl_down_sync(0xffffffffu, b, o);
    }
    if (lane == 0) { sm[wid] = a; sm[wid + 16] = b; }
    __syncthreads();
    if (wid == 0) {
        a = lane < nwarp ? sm[lane] : 0.f;
        b = lane < nwarp ? sm[lane + 16] : 0.f;
#pragma unroll
        for (int o = 16; o > 0; o >>= 1) {
            a += __shfl_down_sync(0xffffffffu, a, o);
            b += __shfl_down_sync(0xffffffffu, b, o);
        }
        if (lane == 0) { sm[32] = a; sm[33] = b; }
    }
    __syncthreads();
    a = sm[32];
    b = sm[33];
    __syncthreads();
}

// ---------------- 1) token-mean pool + LN (+ inv-norm scalar) -----------------
// 256 blocks x 2 frames each: all blocks resident -> one wave, no BW tail.
__global__ __launch_bounds__(POOL_T) void pool_ln_k(
    const float* __restrict__ img, const float* __restrict__ g,
    const float* __restrict__ b) {
    const int tid = threadIdx.x;
    const int c0 = tid, c1 = tid + POOL_T;

    const float4 g0 = __ldg(reinterpret_cast<const float4*>(g) + c0);
    const float4 g1 = __ldg(reinterpret_cast<const float4*>(g) + c1);
    const float4 b0 = __ldg(reinterpret_cast<const float4*>(b) + c0);
    const float4 b1v = __ldg(reinterpret_cast<const float4*>(b) + c1);
    __shared__ float sm[34];

    for (int rep = 0; rep < 2; ++rep) {
        const int f = blockIdx.x * 2 + rep;
        const float4* base = reinterpret_cast<const float4*>(img) + (size_t)f * TK * E4;

        float4 a0 = make_float4(0.f, 0.f, 0.f, 0.f);
        float4 a1 = make_float4(0.f, 0.f, 0.f, 0.f);
        for (int t = 0; t < TK; t += 4) {           // 196 = 49*4, MLP=8
            float4 v[8];
#pragma unroll
            for (int u = 0; u < 4; ++u) {
                v[2 * u]     = __ldcs(base + (size_t)(t + u) * E4 + c0);
                v[2 * u + 1] = __ldcs(base + (size_t)(t + u) * E4 + c1);
            }
#pragma unroll
            for (int u = 0; u < 4; ++u) {
                a0.x += v[2*u].x;   a0.y += v[2*u].y;   a0.z += v[2*u].z;   a0.w += v[2*u].w;
                a1.x += v[2*u+1].x; a1.y += v[2*u+1].y; a1.z += v[2*u+1].z; a1.w += v[2*u+1].w;
            }
        }
        const float inv = 1.0f / (float)TK;
        a0.x *= inv; a0.y *= inv; a0.z *= inv; a0.w *= inv;
        a1.x *= inv; a1.y *= inv; a1.z *= inv; a1.w *= inv;

        float s = a0.x + a0.y + a0.z + a0.w + a1.x + a1.y + a1.z + a1.w;
        float q = a0.x*a0.x + a0.y*a0.y + a0.z*a0.z + a0.w*a0.w
                + a1.x*a1.x + a1.y*a1.y + a1.z*a1.z + a1.w*a1.w;

        blk_reduce2(s, q, sm, POOL_T / 32);
        const float mean = s / (float)EM;
        const float var  = q / (float)EM - mean * mean;
        const float rstd = rsqrtf(var + 1e-5f);

        float4 y0, y1;
        y0.x = (a0.x - mean) * rstd * g0.x + b0.x;
        y0.y = (a0.y - mean) * rstd * g0.y + b0.y;
        y0.z = (a0.z - mean) * rstd * g0.z + b0.z;
        y0.w = (a0.w - mean) * rstd * g0.w + b0.w;
        y1.x = (a1.x - mean) * rstd * g1.x + b1v.x;
        y1.y = (a1.y - mean) * rstd * g1.y + b1v.y;
        y1.z = (a1.z - mean) * rstd * g1.z + b1v.z;
        y1.w = (a1.w - mean) * rstd * g1.w + b1v.w;

        float4* pooled4 = reinterpret_cast<float4*>(g_pooled) + (size_t)f * E4;
        pooled4[c0] = y0;
        pooled4[c1] = y1;

        float q2 = y0.x*y0.x + y0.y*y0.y + y0.z*y0.z + y0.w*y0.w
                 + y1.x*y1.x + y1.y*y1.y + y1.z*y1.z + y1.w*y1.w;
        float dummy = 0.f;
        blk_reduce2(q2, dummy, sm, POOL_T / 32);
        if (tid == 0) g_invn[f] = 1.0f / fmaxf(sqrtf(q2), 1e-8f);
        __syncthreads();
    }
}

// ---------------- 2) txt LN + projection --------------------------------------
__global__ __launch_bounds__(256) void tproj_k(
    const float* __restrict__ x, const float* __restrict__ gg,
    const float* __restrict__ bb, const float* __restrict__ W1,
    const float* __restrict__ b1) {
    __shared__ float st[EM];
    __shared__ float sm[34];
    const int t = threadIdx.x;
    float xs[10];
    float s = 0.f, q = 0.f;
#pragma unroll
    for (int k = 0; k < 10; ++k) {
        int e = t + k * 256;
        xs[k] = __ldg(x + e);
        s += xs[k];
        q += xs[k] * xs[k];
    }
    blk_reduce2(s, q, sm, 8);
    const float mean = s / (float)EM;
    const float var  = q / (float)EM - mean * mean;
    const float rstd = rsqrtf(var + 1e-5f);
#pragma unroll
    for (int k = 0; k < 10; ++k) {
        int e = t + k * 256;
        st[e] = (xs[k] - mean) * rstd * __ldg(gg + e) + __ldg(bb + e);
    }
    __syncthreads();

    const int j = blockIdx.x * 32 + (t & 31);
    const int c = t >> 5;
    const float* wp = W1 + (size_t)(c * 320) * HID + j;
    float acc[4] = {0.f, 0.f, 0.f, 0.f};
    for (int e = 0; e < 320; e += 4) {
#pragma unroll
        for (int u = 0; u < 4; ++u)
            acc[u] += st[c * 320 + e + u] * __ldg(wp + (size_t)(e + u) * HID);
    }
    float v = (acc[0] + acc[1]) + (acc[2] + acc[3]);
    __shared__ float red[8][33];
    red[c][t & 31] = v;
    __syncthreads();
    if (c == 0) {
        float r = 0.f;
#pragma unroll
        for (int si = 0; si < 8; ++si) r += red[si][t & 31];
        g_tproj[j] = r + __ldg(b1 + j);
    }
}

// ---------------- 3a) h-GEMM: 128x128 tile, 8x8 microtile, split-K 9 ----------
__global__ __launch_bounds__(256) void gemm_h_k(const float* __restrict__ Wb) {
    const int z = blockIdx.z;
    const int kb = z * 288;
    const int klen = (z == 8) ? 256 : 288;
    const int NT = klen / 8;

    const int rb = blockIdx.y * 128, cb = blockIdx.x * 128;
    const int t = threadIdx.x;
    const int alr = t >> 1, alk = (t & 1) * 4;   // A: 128 rows x 2 k-quads
    const int bk = t >> 5, bc = (t & 31) * 4;    // B: 8 k x 32 col-quads
    const int ty = t >> 4, tx = t & 15;

    const float* Ap = g_pooled + (size_t)(rb + alr) * EM + kb + alk;
    const float* Bp = Wb + (size_t)(kb + bk) * HID + cb + bc;

    __shared__ __align__(16) float As[2][8][132];
    __shared__ __align__(16) float Bs[2][8][132];

    float4 pa = *reinterpret_cast<const float4*>(Ap);
    float4 pb = *reinterpret_cast<const float4*>(Bp);
    As[0][alk + 0][alr] = pa.x;
    As[0][alk + 1][alr] = pa.y;
    As[0][alk + 2][alr] = pa.z;
    As[0][alk + 3][alr] = pa.w;
    *reinterpret_cast<float4*>(&Bs[0][bk][bc]) = pb;
    __syncthreads();

    float acc[8][8];
#pragma unroll
    for (int i = 0; i < 8; ++i)
#pragma unroll
        for (int j = 0; j < 8; ++j) acc[i][j] = 0.f;

    for (int kt = 0; kt < NT; ++kt) {
        const int buf = kt & 1;
        if (kt + 1 < NT) {
            pa = *reinterpret_cast<const float4*>(Ap + (kt + 1) * 8);
            pb = *reinterpret_cast<const float4*>(Bp + (size_t)(kt + 1) * 8 * HID);
        }
#pragma unroll
        for (int kk = 0; kk < 8; ++kk) {
            float4 a0 = *reinterpret_cast<const float4*>(&As[buf][kk][ty * 8]);
            float4 a1 = *reinterpret_cast<const float4*>(&As[buf][kk][ty * 8 + 4]);
            float4 b0 = *reinterpret_cast<const float4*>(&Bs[buf][kk][tx * 8]);
            float4 b1 = *reinterpret_cast<const float4*>(&Bs[buf][kk][tx * 8 + 4]);
            float ar[8] = {a0.x, a0.y, a0.z, a0.w, a1.x, a1.y, a1.z, a1.w};
            float br[8] = {b0.x, b0.y, b0.z, b0.w, b1.x, b1.y, b1.z, b1.w};
#pragma unroll
            for (int i = 0; i < 8; ++i)
#pragma unroll
                for (int j = 0; j < 8; ++j) acc[i][j] += ar[i] * br[j];
        }
        if (kt + 1 < NT) {
            const int nb = buf ^ 1;
            As[nb][alk + 0][alr] = pa.x;
            As[nb][alk + 1][alr] = pa.y;
            As[nb][alk + 2][alr] = pa.z;
            As[nb][alk + 3][alr] = pa.w;
            *reinterpret_cast<float4*>(&Bs[nb][bk][bc]) = pb;
            __syncthreads();
        }
    }

    float* C = g_hp + (size_t)z * NF * HID;
#pragma unroll
    for (int i = 0; i < 8; ++i) {
        float* cp = C + (size_t)(rb + ty * 8 + i) * HID + cb + tx * 8;
        *reinterpret_cast<float4*>(cp) =
            make_float4(acc[i][0], acc[i][1], acc[i][2], acc[i][3]);
        *reinterpret_cast<float4*>(cp + 4) =
            make_float4(acc[i][4], acc[i][5], acc[i][6], acc[i][7]);
    }
}

// ---------------- 3b) f2f GEMM (top-64 rows), 64x64 tile ----------------------
__global__ __launch_bounds__(256) void gemm_f2f_k() {
    constexpr int KCH = EM / KS_F;
    constexpr int NT  = KCH / 16;

    const float* __restrict__ A = g_pooled;
    const float* __restrict__ B = g_pooled;
    float* __restrict__ C = g_fp + (size_t)blockIdx.z * NTOP * NF;

    const int rb = blockIdx.y * 64, cb = blockIdx.x * 64;
    const int kb = blockIdx.z * KCH;
    const int t  = threadIdx.x;
    const int lr = t >> 2, lk = (t & 3) * 4;
    const int ty = t >> 4, tx = t & 15;

    const int arow = g_order[rb + lr];
    const float* Ap = A + (size_t)arow * EM + kb + lk;
    const float* Bp = B + (size_t)(cb + lr) * EM + kb + lk;

    __shared__ __align__(16) float As[2][16][68];
    __shared__ __align__(16) float Bs[2][16][68];

    float4 pa = *reinterpret_cast<const float4*>(Ap);
    float4 pb = *reinterpret_cast<const float4*>(Bp);
    As[0][lk + 0][lr] = pa.x;
    As[0][lk + 1][lr] = pa.y;
    As[0][lk + 2][lr] = pa.z;
    As[0][lk + 3][lr] = pa.w;
    Bs[0][lk + 0][lr] = pb.x;
    Bs[0][lk + 1][lr] = pb.y;
    Bs[0][lk + 2][lr] = pb.z;
    Bs[0][lk + 3][lr] = pb.w;
    __syncthreads();

    float acc[4][4];
#pragma unroll
    for (int i = 0; i < 4; ++i)
#pragma unroll
        for (int j = 0; j < 4; ++j) acc[i][j] = 0.f;

    for (int kt = 0; kt < NT; ++kt) {
        const int buf = kt & 1;
        if (kt + 1 < NT) {
            pa = *reinterpret_cast<const float4*>(Ap + (kt + 1) * 16);
            pb = *reinterpret_cast<const float4*>(Bp + (kt + 1) * 16);
        }
#pragma unroll
        for (int kk = 0; kk < 16; ++kk) {
            float4 av = *reinterpret_cast<const float4*>(&As[buf][kk][ty * 4]);
            float4 bv = *reinterpret_cast<const float4*>(&Bs[buf][kk][tx * 4]);
            float ar[4] = {av.x, av.y, av.z, av.w};
            float br[4] = {bv.x, bv.y, bv.z, bv.w};
#pragma unroll
            for (int i = 0; i < 4; ++i)
#pragma unroll
                for (int j = 0; j < 4; ++j) acc[i][j] += ar[i] * br[j];
        }
        if (kt + 1 < NT) {
            const int nb = buf ^ 1;
            As[nb][lk + 0][lr] = pa.x;
            As[nb][lk + 1][lr] = pa.y;
            As[nb][lk + 2][lr] = pa.z;
            As[nb][lk + 3][lr] = pa.w;
            Bs[nb][lk + 0][lr] = pb.x;
            Bs[nb][lk + 1][lr] = pb.y;
            Bs[nb][lk + 2][lr] = pb.z;
            Bs[nb][lk + 3][lr] = pb.w;
            __syncthreads();
        }
    }

    float rs[4], cs[4];
#pragma unroll
    for (int r = 0; r < 4; ++r) rs[r] = g_invn[g_order[rb + ty * 4 + r]];
#pragma unroll
    for (int j = 0; j < 4; ++j) cs[j] = g_invn[cb + tx * 4 + j];
#pragma unroll
    for (int i = 0; i < 4; ++i) {
        float4 v = make_float4(acc[i][0] * rs[i] * cs[0], acc[i][1] * rs[i] * cs[1],
                               acc[i][2] * rs[i] * cs[2], acc[i][3] * rs[i] * cs[3]);
        *reinterpret_cast<float4*>(C + (size_t)(rb + ty * 4 + i) * 512 + cb + tx * 4) = v;
    }
}

// ---------------- 4) gates: sigmoid(relu(h_sum + tproj) @ W2 + b2) ------------
__global__ __launch_bounds__(128) void gates_k(
    const float* __restrict__ W2, const float* __restrict__ b2) {
    const int n = blockIdx.x, tid = threadIdx.x;   // tid = float4 column
    float4 hv = *(reinterpret_cast<const float4*>(g_tproj) + tid);
#pragma unroll
    for (int s = 0; s < KS_H; ++s) {
        float4 p = *(reinterpret_cast<const float4*>(g_hp + (size_t)s * NF * HID + (size_t)n * HID) + tid);
        hv.x += p.x; hv.y += p.y; hv.z += p.z; hv.w += p.w;
    }
    const float4 w = __ldg(reinterpret_cast<const float4*>(W2) + tid);
    float v = fmaxf(hv.x, 0.f) * w.x + fmaxf(hv.y, 0.f) * w.y
            + fmaxf(hv.z, 0.f) * w.z + fmaxf(hv.w, 0.f) * w.w;
    __shared__ float sm[4];
    int lane = tid & 31, wid = tid >> 5;
#pragma unroll
    for (int o = 16; o > 0; o >>= 1) v += __shfl_down_sync(0xffffffffu, v, o);
    if (lane == 0) sm[wid] = v;
    __syncthreads();
    if (tid == 0) {
        float z = sm[0] + sm[1] + sm[2] + sm[3] + __ldg(b2);
        g_gates[n] = 1.0f / (1.0f + expf(-z));
    }
}

// ---------------- 5) stable descending rank-sort ------------------------------
__global__ __launch_bounds__(NF) void sort_k() {
    __shared__ unsigned long long keys[NF];
    const int i = threadIdx.x;
    unsigned int bits = __float_as_uint(g_gates[i]);
    keys[i] = ((unsigned long long)(0xFFFFFFFFu - bits) << 32) | (unsigned int)i;
    __syncthreads();
    const unsigned long long me = keys[i];
    int r = 0;
    for (int j = 0; j < NF; ++j) r += (keys[j] < me) ? 1 : 0;
    g_order[r] = i;
}

// ---------------- 6) reduce f2f partials -> similarity bitmask ----------------
__global__ __launch_bounds__(128) void mask_k() {
    const int r = blockIdx.x, t = threadIdx.x;
    float4 s = *(reinterpret_cast<const float4*>(g_fp + (size_t)r * NF) + t);
#pragma unroll
    for (int sp = 1; sp < KS_F; ++sp) {
        float4 p = *(reinterpret_cast<const float4*>(g_fp + (size_t)sp * NTOP * NF + (size_t)r * NF) + t);
        s.x += p.x; s.y += p.y; s.z += p.z; s.w += p.w;
    }
    __shared__ unsigned char nib[128];
    unsigned int n = (s.x > 0.98f ? 1u : 0u) | (s.y > 0.98f ? 2u : 0u)
                   | (s.z > 0.98f ? 4u : 0u) | (s.w > 0.98f ? 8u : 0u);
    nib[t] = (unsigned char)n;
    __syncthreads();
    if (t < 16) {
        unsigned int w = 0;
#pragma unroll
        for (int b = 0; b < 8; ++b) w |= ((unsigned int)nib[8 * t + b]) << (4 * b);
        g_mask[r * 16 + t] = w;
    }
}

// ---------------- 7) greedy selection scan + output ---------------------------
__global__ __launch_bounds__(NF) void scan_k(float* __restrict__ out) {
    __shared__ int s_count, s_done, s_cur, s_take;
    __shared__ unsigned char vis[NF], sel[NF];
    __shared__ unsigned int msk[NTOP * 16];
    const int tid = threadIdx.x;
    vis[tid] = 0;
    sel[tid] = 0;
    if (tid == 0) { s_count = 0; s_done = 0; }
    msk[tid] = g_mask[tid];
    msk[tid + 512] = g_mask[tid + 512];
    __syncthreads();
    for (int pos = 0; pos < NF; ++pos) {
        if (tid == 0) {
            if (s_count >= 32) {
                s_done = 1;
            } else {
                int cur = g_order[pos];
                s_cur = cur;
                int take = vis[cur] ? 0 : 1;
                s_take = take;
                if (take) { sel[cur] = 1; s_count++; }
            }
        }
        __syncthreads();
        if (s_done) break;
        if (s_take) {
            bool hit;
            if (pos < NTOP) {
                hit = (msk[pos * 16 + (tid >> 5)] >> (tid & 31)) & 1u;
            } else {                               // exact fallback (not hit on normal data)
                const float* a = g_pooled + (size_t)s_cur * EM;
                const float* bb = g_pooled + (size_t)tid * EM;
                float d = 0.f;
                for (int e = 0; e < EM; ++e) d += a[e] * bb[e];
                hit = d * g_invn[s_cur] * g_invn[tid] > 0.98f;
            }
            if (hit) vis[tid] = 1;
        }
        __syncthreads();
    }
    __syncthreads();
    out[tid] = (float)sel[tid];
    out[NF + tid] = g_gates[tid];
}

// ---------------- launch ------------------------------------------------------
extern "C" void kernel_launch(void* const* d_in, const int* in_sizes, int n_in,
                              void* d_out, int out_size) {
    const float* img    = (const float*)d_in[0];
    const float* txt    = (const float*)d_in[1];
    const float* ln_t_g = (const float*)d_in[2];
    const float* ln_t_b = (const float*)d_in[3];
    const float* ln_l_g = (const float*)d_in[4];
    const float* ln_l_b = (const float*)d_in[5];
    const float* W1     = (const float*)d_in[6];
    const float* b1     = (const float*)d_in[7];
    const float* W2     = (const float*)d_in[8];
    const float* b2     = (const float*)d_in[9];
    float* out = (float*)d_out;

    pool_ln_k<<<NF / 2, POOL_T>>>(img, ln_l_g, ln_l_b);
    tproj_k<<<16, 256>>>(txt, ln_t_g, ln_t_b, W1, b1);
    gemm_h_k<<<dim3(4, 4, KS_H), 256>>>(W1 + (size_t)EM * HID);
    gates_k<<<NF, 128>>>(W2, b2);
    sort_k<<<1, NF>>>();
    gemm_f2f_k<<<dim3(8, 1, KS_F), 256>>>();
    mask_k<<<NTOP, 128>>>();
    scan_k<<<1, NF>>>(out);
}

// round 8
// speedup vs baseline: 1.0532x; 1.0532x over previous
#include <cuda_runtime.h>
#include <math.h>

#define NF   512
#define TK   196
#define EM   2560
#define HID  512
#define E4   (EM/4)
#define NTOP 64
#define KS_H 9
#define KS_F 8

// ---------------- scratch (static device globals) ----------------------------
__device__ float g_pooled[NF * EM];         // layer-normed pooled features
__device__ float g_invn[NF];                // 1/||pooled_ln|| per frame
__device__ float g_tproj[HID];              // txt_ln @ W1_top + b1
__device__ float g_hp[KS_H * NF * HID];     // split-K partials of pooled_ln @ W1_bot
__device__ float g_fp[KS_F * NTOP * NF];    // split-K partials of top-64 f2f rows
__device__ float g_gates[NF];
__device__ int   g_order[NF];
__device__ unsigned int g_mask[NTOP * 16];  // f2f>0.98 bitmask for top-64 rows

// ---------------- block reduce of two scalars --------------------------------
__device__ __forceinline__ void blk_reduce2(float& a, float& b, float* sm, int nwarp) {
    int lane = threadIdx.x & 31, wid = threadIdx.x >> 5;
#pragma unroll
    for (int o = 16; o > 0; o >>= 1) {
        a += __shfl_down_sync(0xffffffffu, a, o);
        b += __shfl_down_sync(0xffffffffu, b, o);
    }
    if (lane == 0) { sm[wid] = a; sm[wid + 16] = b; }
    __syncthreads();
    if (wid == 0) {
        a = lane < nwarp ? sm[lane] : 0.f;
        b = lane < nwarp ? sm[lane + 16] : 0.f;
#pragma unroll
        for (int o = 16; o > 0; o >>= 1) {
            a += __shfl_down_sync(0xffffffffu, a, o);
            b += __shfl_down_sync(0xffffffffu, b, o);
        }
        if (lane == 0) { sm[32] = a; sm[33] = b; }
    }
    __syncthreads();
    a = sm[32];
    b = sm[33];
    __syncthreads();
}

// ---------------- 1) token-mean pool + LN (+ inv-norm scalar) -----------------
// 512 blocks x 128 threads (5 float4 cols each): ALL blocks resident -> 1 wave.
__global__ __launch_bounds__(128) void pool_ln_k(
    const float* __restrict__ img, const float* __restrict__ g,
    const float* __restrict__ b) {
    const int f = blockIdx.x, tid = threadIdx.x;
    const float4* base = reinterpret_cast<const float4*>(img) + (size_t)f * TK * E4;

    float4 a[5];
#pragma unroll
    for (int k = 0; k < 5; ++k) a[k] = make_float4(0.f, 0.f, 0.f, 0.f);

    for (int t = 0; t < TK; ++t) {                  // MLP=5 per thread, 16 warps/blk-pair
        float4 v[5];
#pragma unroll
        for (int k = 0; k < 5; ++k)
            v[k] = __ldcs(base + (size_t)t * E4 + tid + k * 128);
#pragma unroll
        for (int k = 0; k < 5; ++k) {
            a[k].x += v[k].x; a[k].y += v[k].y; a[k].z += v[k].z; a[k].w += v[k].w;
        }
    }
    const float inv = 1.0f / (float)TK;
    float s = 0.f, q = 0.f;
#pragma unroll
    for (int k = 0; k < 5; ++k) {
        a[k].x *= inv; a[k].y *= inv; a[k].z *= inv; a[k].w *= inv;
        s += a[k].x + a[k].y + a[k].z + a[k].w;
        q += a[k].x*a[k].x + a[k].y*a[k].y + a[k].z*a[k].z + a[k].w*a[k].w;
    }

    __shared__ float sm[34];
    blk_reduce2(s, q, sm, 4);
    const float mean = s / (float)EM;
    const float var  = q / (float)EM - mean * mean;
    const float rstd = rsqrtf(var + 1e-5f);

    float q2 = 0.f;
    float4 y[5];
#pragma unroll
    for (int k = 0; k < 5; ++k) {
        const float4 gv = __ldg(reinterpret_cast<const float4*>(g) + tid + k * 128);
        const float4 bv = __ldg(reinterpret_cast<const float4*>(b) + tid + k * 128);
        y[k].x = (a[k].x - mean) * rstd * gv.x + bv.x;
        y[k].y = (a[k].y - mean) * rstd * gv.y + bv.y;
        y[k].z = (a[k].z - mean) * rstd * gv.z + bv.z;
        y[k].w = (a[k].w - mean) * rstd * gv.w + bv.w;
        q2 += y[k].x*y[k].x + y[k].y*y[k].y + y[k].z*y[k].z + y[k].w*y[k].w;
    }
    float4* pooled4 = reinterpret_cast<float4*>(g_pooled) + (size_t)f * E4;
#pragma unroll
    for (int k = 0; k < 5; ++k) pooled4[tid + k * 128] = y[k];

    float dummy = 0.f;
    blk_reduce2(q2, dummy, sm, 4);
    if (tid == 0) g_invn[f] = 1.0f / fmaxf(sqrtf(q2), 1e-8f);
}

// ---------------- 2) txt LN + projection --------------------------------------
__global__ __launch_bounds__(256) void tproj_k(
    const float* __restrict__ x, const float* __restrict__ gg,
    const float* __restrict__ bb, const float* __restrict__ W1,
    const float* __restrict__ b1) {
    __shared__ float st[EM];
    __shared__ float sm[34];
    const int t = threadIdx.x;
    float xs[10];
    float s = 0.f, q = 0.f;
#pragma unroll
    for (int k = 0; k < 10; ++k) {
        int e = t + k * 256;
        xs[k] = __ldg(x + e);
        s += xs[k];
        q += xs[k] * xs[k];
    }
    blk_reduce2(s, q, sm, 8);
    const float mean = s / (float)EM;
    const float var  = q / (float)EM - mean * mean;
    const float rstd = rsqrtf(var + 1e-5f);
#pragma unroll
    for (int k = 0; k < 10; ++k) {
        int e = t + k * 256;
        st[e] = (xs[k] - mean) * rstd * __ldg(gg + e) + __ldg(bb + e);
    }
    __syncthreads();

    const int j = blockIdx.x * 32 + (t & 31);
    const int c = t >> 5;
    const float* wp = W1 + (size_t)(c * 320) * HID + j;
    float acc[4] = {0.f, 0.f, 0.f, 0.f};
    for (int e = 0; e < 320; e += 4) {
#pragma unroll
        for (int u = 0; u < 4; ++u)
            acc[u] += st[c * 320 + e + u] * __ldg(wp + (size_t)(e + u) * HID);
    }
    float v = (acc[0] + acc[1]) + (acc[2] + acc[3]);
    __shared__ float red[8][33];
    red[c][t & 31] = v;
    __syncthreads();
    if (c == 0) {
        float r = 0.f;
#pragma unroll
        for (int si = 0; si < 8; ++si) r += red[si][t & 31];
        g_tproj[j] = r + __ldg(b1 + j);
    }
}

// ---------------- 3a) h-GEMM: 128x128 tile, 8x8 microtile, split-K 9 ----------
__global__ __launch_bounds__(256) void gemm_h_k(const float* __restrict__ Wb) {
    const int z = blockIdx.z;
    const int kb = z * 288;
    const int klen = (z == 8) ? 256 : 288;
    const int NT = klen / 8;

    const int rb = blockIdx.y * 128, cb = blockIdx.x * 128;
    const int t = threadIdx.x;
    const int alr = t >> 1, alk = (t & 1) * 4;   // A: 128 rows x 2 k-quads
    const int bk = t >> 5, bc = (t & 31) * 4;    // B: 8 k x 32 col-quads
    const int ty = t >> 4, tx = t & 15;

    const float* Ap = g_pooled + (size_t)(rb + alr) * EM + kb + alk;
    const float* Bp = Wb + (size_t)(kb + bk) * HID + cb + bc;

    __shared__ __align__(16) float As[2][8][132];
    __shared__ __align__(16) float Bs[2][8][132];

    float4 pa = *reinterpret_cast<const float4*>(Ap);
    float4 pb = *reinterpret_cast<const float4*>(Bp);
    As[0][alk + 0][alr] = pa.x;
    As[0][alk + 1][alr] = pa.y;
    As[0][alk + 2][alr] = pa.z;
    As[0][alk + 3][alr] = pa.w;
    *reinterpret_cast<float4*>(&Bs[0][bk][bc]) = pb;
    __syncthreads();

    float acc[8][8];
#pragma unroll
    for (int i = 0; i < 8; ++i)
#pragma unroll
        for (int j = 0; j < 8; ++j) acc[i][j] = 0.f;

    for (int kt = 0; kt < NT; ++kt) {
        const int buf = kt & 1;
        if (kt + 1 < NT) {
            pa = *reinterpret_cast<const float4*>(Ap + (kt + 1) * 8);
            pb = *reinterpret_cast<const float4*>(Bp + (size_t)(kt + 1) * 8 * HID);
        }
#pragma unroll
        for (int kk = 0; kk < 8; ++kk) {
            float4 a0 = *reinterpret_cast<const float4*>(&As[buf][kk][ty * 8]);
            float4 a1 = *reinterpret_cast<const float4*>(&As[buf][kk][ty * 8 + 4]);
            float4 b0 = *reinterpret_cast<const float4*>(&Bs[buf][kk][tx * 8]);
            float4 b1 = *reinterpret_cast<const float4*>(&Bs[buf][kk][tx * 8 + 4]);
            float ar[8] = {a0.x, a0.y, a0.z, a0.w, a1.x, a1.y, a1.z, a1.w};
            float br[8] = {b0.x, b0.y, b0.z, b0.w, b1.x, b1.y, b1.z, b1.w};
#pragma unroll
            for (int i = 0; i < 8; ++i)
#pragma unroll
                for (int j = 0; j < 8; ++j) acc[i][j] += ar[i] * br[j];
        }
        if (kt + 1 < NT) {
            const int nb = buf ^ 1;
            As[nb][alk + 0][alr] = pa.x;
            As[nb][alk + 1][alr] = pa.y;
            As[nb][alk + 2][alr] = pa.z;
            As[nb][alk + 3][alr] = pa.w;
            *reinterpret_cast<float4*>(&Bs[nb][bk][bc]) = pb;
            __syncthreads();
        }
    }

    float* C = g_hp + (size_t)z * NF * HID;
#pragma unroll
    for (int i = 0; i < 8; ++i) {
        float* cp = C + (size_t)(rb + ty * 8 + i) * HID + cb + tx * 8;
        *reinterpret_cast<float4*>(cp) =
            make_float4(acc[i][0], acc[i][1], acc[i][2], acc[i][3]);
        *reinterpret_cast<float4*>(cp + 4) =
            make_float4(acc[i][4], acc[i][5], acc[i][6], acc[i][7]);
    }
}

// ---------------- 3b) f2f GEMM (top-64 rows), 64x64 tile ----------------------
__global__ __launch_bounds__(256) void gemm_f2f_k() {
    constexpr int KCH = EM / KS_F;
    constexpr int NT  = KCH / 16;

    const float* __restrict__ A = g_pooled;
    const float* __restrict__ B = g_pooled;
    float* __restrict__ C = g_fp + (size_t)blockIdx.z * NTOP * NF;

    const int rb = blockIdx.y * 64, cb = blockIdx.x * 64;
    const int kb = blockIdx.z * KCH;
    const int t  = threadIdx.x;
    const int lr = t >> 2, lk = (t & 3) * 4;
    const int ty = t >> 4, tx = t & 15;

    const int arow = g_order[rb + lr];
    const float* Ap = A + (size_t)arow * EM + kb + lk;
    const float* Bp = B + (size_t)(cb + lr) * EM + kb + lk;

    __shared__ __align__(16) float As[2][16][68];
    __shared__ __align__(16) float Bs[2][16][68];

    float4 pa = *reinterpret_cast<const float4*>(Ap);
    float4 pb = *reinterpret_cast<const float4*>(Bp);
    As[0][lk + 0][lr] = pa.x;
    As[0][lk + 1][lr] = pa.y;
    As[0][lk + 2][lr] = pa.z;
    As[0][lk + 3][lr] = pa.w;
    Bs[0][lk + 0][lr] = pb.x;
    Bs[0][lk + 1][lr] = pb.y;
    Bs[0][lk + 2][lr] = pb.z;
    Bs[0][lk + 3][lr] = pb.w;
    __syncthreads();

    float acc[4][4];
#pragma unroll
    for (int i = 0; i < 4; ++i)
#pragma unroll
        for (int j = 0; j < 4; ++j) acc[i][j] = 0.f;

    for (int kt = 0; kt < NT; ++kt) {
        const int buf = kt & 1;
        if (kt + 1 < NT) {
            pa = *reinterpret_cast<const float4*>(Ap + (kt + 1) * 16);
            pb = *reinterpret_cast<const float4*>(Bp + (kt + 1) * 16);
        }
#pragma unroll
        for (int kk = 0; kk < 16; ++kk) {
            float4 av = *reinterpret_cast<const float4*>(&As[buf][kk][ty * 4]);
            float4 bv = *reinterpret_cast<const float4*>(&Bs[buf][kk][tx * 4]);
            float ar[4] = {av.x, av.y, av.z, av.w};
            float br[4] = {bv.x, bv.y, bv.z, bv.w};
#pragma unroll
            for (int i = 0; i < 4; ++i)
#pragma unroll
                for (int j = 0; j < 4; ++j) acc[i][j] += ar[i] * br[j];
        }
        if (kt + 1 < NT) {
            const int nb = buf ^ 1;
            As[nb][lk + 0][lr] = pa.x;
            As[nb][lk + 1][lr] = pa.y;
            As[nb][lk + 2][lr] = pa.z;
            As[nb][lk + 3][lr] = pa.w;
            Bs[nb][lk + 0][lr] = pb.x;
            Bs[nb][lk + 1][lr] = pb.y;
            Bs[nb][lk + 2][lr] = pb.z;
            Bs[nb][lk + 3][lr] = pb.w;
            __syncthreads();
        }
    }

    float rs[4], cs[4];
#pragma unroll
    for (int r = 0; r < 4; ++r) rs[r] = g_invn[g_order[rb + ty * 4 + r]];
#pragma unroll
    for (int j = 0; j < 4; ++j) cs[j] = g_invn[cb + tx * 4 + j];
#pragma unroll
    for (int i = 0; i < 4; ++i) {
        float4 v = make_float4(acc[i][0] * rs[i] * cs[0], acc[i][1] * rs[i] * cs[1],
                               acc[i][2] * rs[i] * cs[2], acc[i][3] * rs[i] * cs[3]);
        *reinterpret_cast<float4*>(C + (size_t)(rb + ty * 4 + i) * 512 + cb + tx * 4) = v;
    }
}

// ---------------- 4) gates: sigmoid(relu(h_sum + tproj) @ W2 + b2) ------------
__global__ __launch_bounds__(128) void gates_k(
    const float* __restrict__ W2, const float* __restrict__ b2) {
    const int n = blockIdx.x, tid = threadIdx.x;   // tid = float4 column
    float4 hv = *(reinterpret_cast<const float4*>(g_tproj) + tid);
#pragma unroll
    for (int s = 0; s < KS_H; ++s) {
        float4 p = *(reinterpret_cast<const float4*>(g_hp + (size_t)s * NF * HID + (size_t)n * HID) + tid);
        hv.x += p.x; hv.y += p.y; hv.z += p.z; hv.w += p.w;
    }
    const float4 w = __ldg(reinterpret_cast<const float4*>(W2) + tid);
    float v = fmaxf(hv.x, 0.f) * w.x + fmaxf(hv.y, 0.f) * w.y
            + fmaxf(hv.z, 0.f) * w.z + fmaxf(hv.w, 0.f) * w.w;
    __shared__ float sm[4];
    int lane = tid & 31, wid = tid >> 5;
#pragma unroll
    for (int o = 16; o > 0; o >>= 1) v += __shfl_down_sync(0xffffffffu, v, o);
    if (lane == 0) sm[wid] = v;
    __syncthreads();
    if (tid == 0) {
        float z = sm[0] + sm[1] + sm[2] + sm[3] + __ldg(b2);
        g_gates[n] = 1.0f / (1.0f + expf(-z));
    }
}

// ---------------- 5) stable descending rank-sort ------------------------------
__global__ __launch_bounds__(NF) void sort_k() {
    __shared__ unsigned long long keys[NF];
    const int i = threadIdx.x;
    unsigned int bits = __float_as_uint(g_gates[i]);
    keys[i] = ((unsigned long long)(0xFFFFFFFFu - bits) << 32) | (unsigned int)i;
    __syncthreads();
    const unsigned long long me = keys[i];
    int r = 0;
    for (int j = 0; j < NF; ++j) r += (keys[j] < me) ? 1 : 0;
    g_order[r] = i;
}

// ---------------- 6) reduce f2f partials -> similarity bitmask ----------------
__global__ __launch_bounds__(128) void mask_k() {
    const int r = blockIdx.x, t = threadIdx.x;
    float4 s = *(reinterpret_cast<const float4*>(g_fp + (size_t)r * NF) + t);
#pragma unroll
    for (int sp = 1; sp < KS_F; ++sp) {
        float4 p = *(reinterpret_cast<const float4*>(g_fp + (size_t)sp * NTOP * NF + (size_t)r * NF) + t);
        s.x += p.x; s.y += p.y; s.z += p.z; s.w += p.w;
    }
    __shared__ unsigned char nib[128];
    unsigned int n = (s.x > 0.98f ? 1u : 0u) | (s.y > 0.98f ? 2u : 0u)
                   | (s.z > 0.98f ? 4u : 0u) | (s.w > 0.98f ? 8u : 0u);
    nib[t] = (unsigned char)n;
    __syncthreads();
    if (t < 16) {
        unsigned int w = 0;
#pragma unroll
        for (int b = 0; b < 8; ++b) w |= ((unsigned int)nib[8 * t + b]) << (4 * b);
        g_mask[r * 16 + t] = w;
    }
}

// ---------------- 7) greedy selection scan + output ---------------------------
__global__ __launch_bounds__(NF) void scan_k(float* __restrict__ out) {
    __shared__ int s_count, s_done, s_cur, s_take;
    __shared__ unsigned char vis[NF], sel[NF];
    __shared__ unsigned int msk[NTOP * 16];
    const int tid = threadIdx.x;
    vis[tid] = 0;
    sel[tid] = 0;
    if (tid == 0) { s_count = 0; s_done = 0; }
    msk[tid] = g_mask[tid];
    msk[tid + 512] = g_mask[tid + 512];
    __syncthreads();
    for (int pos = 0; pos < NF; ++pos) {
        if (tid == 0) {
            if (s_count >= 32) {
                s_done = 1;
            } else {
                int cur = g_order[pos];
                s_cur = cur;
                int take = vis[cur] ? 0 : 1;
                s_take = take;
                if (take) { sel[cur] = 1; s_count++; }
            }
        }
        __syncthreads();
        if (s_done) break;
        if (s_take) {
            bool hit;
            if (pos < NTOP) {
                hit = (msk[pos * 16 + (tid >> 5)] >> (tid & 31)) & 1u;
            } else {                               // exact fallback (not hit on normal data)
                const float* a = g_pooled + (size_t)s_cur * EM;
                const float* bb = g_pooled + (size_t)tid * EM;
                float d = 0.f;
                for (int e = 0; e < EM; ++e) d += a[e] * bb[e];
                hit = d * g_invn[s_cur] * g_invn[tid] > 0.98f;
            }
            if (hit) vis[tid] = 1;
        }
        __syncthreads();
    }
    __syncthreads();
    out[tid] = (float)sel[tid];
    out[NF + tid] = g_gates[tid];
}

// ---------------- launch ------------------------------------------------------
extern "C" void kernel_launch(void* const* d_in, const int* in_sizes, int n_in,
                              void* d_out, int out_size) {
    const float* img    = (const float*)d_in[0];
    const float* txt    = (const float*)d_in[1];
    const float* ln_t_g = (const float*)d_in[2];
    const float* ln_t_b = (const float*)d_in[3];
    const float* ln_l_g = (const float*)d_in[4];
    const float* ln_l_b = (const float*)d_in[5];
    const float* W1     = (const float*)d_in[6];
    const float* b1     = (const float*)d_in[7];
    const float* W2     = (const float*)d_in[8];
    const float* b2     = (const float*)d_in[9];
    float* out = (float*)d_out;

    pool_ln_k<<<NF, 128>>>(img, ln_l_g, ln_l_b);
    tproj_k<<<16, 256>>>(txt, ln_t_g, ln_t_b, W1, b1);
    gemm_h_k<<<dim3(4, 4, KS_H), 256>>>(W1 + (size_t)EM * HID);
    gates_k<<<NF, 128>>>(W2, b2);
    sort_k<<<1, NF>>>();
    gemm_f2f_k<<<dim3(8, 1, KS_F), 256>>>();
    mask_k<<<NTOP, 128>>>();
    scan_k<<<1, NF>>>(out);
}

// round 9
// speedup vs baseline: 1.1714x; 1.1123x over previous
#include <cuda_runtime.h>
#include <math.h>

#define NF   512
#define TK   196
#define EM   2560
#define HID  512
#define E4   (EM/4)
#define POOL_T 320
#define NTOP 64
#define KS_H 9
#define KS_F 8

// ---------------- scratch (static device globals) ----------------------------
__device__ float g_pooled[NF * EM];         // layer-normed pooled features
__device__ float g_invn[NF];                // 1/||pooled_ln|| per frame
__device__ float g_tproj[HID];              // txt_ln @ W1_top + b1
__device__ float g_hp[KS_H * NF * HID];     // split-K partials of pooled_ln @ W1_bot
__device__ float g_fp[KS_F * NTOP * NF];    // split-K partials of top-64 f2f rows
__device__ float g_gates[NF];
__device__ int   g_order[NF];
__device__ unsigned int g_mask[NTOP * 16];  // f2f>0.98 bitmask for top-64 rows

// ---------------- block reduce of two scalars --------------------------------
__device__ __forceinline__ void blk_reduce2(float& a, float& b, float* sm, int nwarp) {
    int lane = threadIdx.x & 31, wid = threadIdx.x >> 5;
#pragma unroll
    for (int o = 16; o > 0; o >>= 1) {
        a += __shfl_down_sync(0xffffffffu, a, o);
        b += __shfl_down_sync(0xffffffffu, b, o);
    }
    if (lane == 0) { sm[wid] = a; sm[wid + 16] = b; }
    __syncthreads();
    if (wid == 0) {
        a = lane < nwarp ? sm[lane] : 0.f;
        b = lane < nwarp ? sm[lane + 16] : 0.f;
#pragma unroll
        for (int o = 16; o > 0; o >>= 1) {
            a += __shfl_down_sync(0xffffffffu, a, o);
            b += __shfl_down_sync(0xffffffffu, b, o);
        }
        if (lane == 0) { sm[32] = a; sm[33] = b; }
    }
    __syncthreads();
    a = sm[32];
    b = sm[33];
    __syncthreads();
}

// ---------------- 1) pool+LN (blocks 0..511) / txt-LN+proj (blocks 512..527) --
__global__ __launch_bounds__(POOL_T) void pool_tproj_k(
    const float* __restrict__ img, const float* __restrict__ g,
    const float* __restrict__ b,
    const float* __restrict__ xt, const float* __restrict__ gt,
    const float* __restrict__ bt, const float* __restrict__ W1,
    const float* __restrict__ b1) {
    const int tid = threadIdx.x;

    if (blockIdx.x < NF) {
        // ---------------- pool path (identical to R6 229.4 baseline) ----------
        const int f = blockIdx.x;
        const float4* base = reinterpret_cast<const float4*>(img) + (size_t)f * TK * E4;
        const int c0 = tid, c1 = tid + POOL_T;

        float4 a0 = make_float4(0.f, 0.f, 0.f, 0.f);
        float4 a1 = make_float4(0.f, 0.f, 0.f, 0.f);
        for (int t = 0; t < TK; t += 4) {           // 196 = 49*4, MLP=8
            float4 v[8];
#pragma unroll
            for (int u = 0; u < 4; ++u) {
                v[2 * u]     = __ldcs(base + (size_t)(t + u) * E4 + c0);
                v[2 * u + 1] = __ldcs(base + (size_t)(t + u) * E4 + c1);
            }
#pragma unroll
            for (int u = 0; u < 4; ++u) {
                a0.x += v[2*u].x;   a0.y += v[2*u].y;   a0.z += v[2*u].z;   a0.w += v[2*u].w;
                a1.x += v[2*u+1].x; a1.y += v[2*u+1].y; a1.z += v[2*u+1].z; a1.w += v[2*u+1].w;
            }
        }
        const float inv = 1.0f / (float)TK;
        a0.x *= inv; a0.y *= inv; a0.z *= inv; a0.w *= inv;
        a1.x *= inv; a1.y *= inv; a1.z *= inv; a1.w *= inv;

        float s = a0.x + a0.y + a0.z + a0.w + a1.x + a1.y + a1.z + a1.w;
        float q = a0.x*a0.x + a0.y*a0.y + a0.z*a0.z + a0.w*a0.w
                + a1.x*a1.x + a1.y*a1.y + a1.z*a1.z + a1.w*a1.w;

        __shared__ float sm[34];
        blk_reduce2(s, q, sm, POOL_T / 32);
        const float mean = s / (float)EM;
        const float var  = q / (float)EM - mean * mean;
        const float rstd = rsqrtf(var + 1e-5f);

        const float4 g0 = __ldg(reinterpret_cast<const float4*>(g) + c0);
        const float4 g1 = __ldg(reinterpret_cast<const float4*>(g) + c1);
        const float4 b0 = __ldg(reinterpret_cast<const float4*>(b) + c0);
        const float4 b1v = __ldg(reinterpret_cast<const float4*>(b) + c1);

        float4 y0, y1;
        y0.x = (a0.x - mean) * rstd * g0.x + b0.x;
        y0.y = (a0.y - mean) * rstd * g0.y + b0.y;
        y0.z = (a0.z - mean) * rstd * g0.z + b0.z;
        y0.w = (a0.w - mean) * rstd * g0.w + b0.w;
        y1.x = (a1.x - mean) * rstd * g1.x + b1v.x;
        y1.y = (a1.y - mean) * rstd * g1.y + b1v.y;
        y1.z = (a1.z - mean) * rstd * g1.z + b1v.z;
        y1.w = (a1.w - mean) * rstd * g1.w + b1v.w;

        float4* pooled4 = reinterpret_cast<float4*>(g_pooled) + (size_t)f * E4;
        pooled4[c0] = y0;
        pooled4[c1] = y1;

        float q2 = y0.x*y0.x + y0.y*y0.y + y0.z*y0.z + y0.w*y0.w
                 + y1.x*y1.x + y1.y*y1.y + y1.z*y1.z + y1.w*y1.w;
        float dummy = 0.f;
        blk_reduce2(q2, dummy, sm, POOL_T / 32);
        if (tid == 0) g_invn[f] = 1.0f / fmaxf(sqrtf(q2), 1e-8f);
    } else {
        // ---------------- tproj path: txt LN + 32 output columns per block ----
        __shared__ float st[EM];
        __shared__ float smt[34];
        __shared__ float red[10][33];
        const int blk = blockIdx.x - NF;            // 0..15
        float xs[8];
        float s = 0.f, q = 0.f;
#pragma unroll
        for (int k = 0; k < 8; ++k) {               // 320*8 = 2560
            int e = tid + k * POOL_T;
            xs[k] = __ldg(xt + e);
            s += xs[k];
            q += xs[k] * xs[k];
        }
        blk_reduce2(s, q, smt, POOL_T / 32);
        const float mean = s / (float)EM;
        const float var  = q / (float)EM - mean * mean;
        const float rstd = rsqrtf(var + 1e-5f);
#pragma unroll
        for (int k = 0; k < 8; ++k) {
            int e = tid + k * POOL_T;
            st[e] = (xs[k] - mean) * rstd * __ldg(gt + e) + __ldg(bt + e);
        }
        __syncthreads();

        const int j = blk * 32 + (tid & 31);
        const int c = tid >> 5;                     // 10 warps, 256-elem K-chunks
        const float* wp = W1 + (size_t)(c * 256) * HID + j;
        float acc[4] = {0.f, 0.f, 0.f, 0.f};
        for (int e = 0; e < 256; e += 4) {
#pragma unroll
            for (int u = 0; u < 4; ++u)
                acc[u] += st[c * 256 + e + u] * __ldg(wp + (size_t)(e + u) * HID);
        }
        float v = (acc[0] + acc[1]) + (acc[2] + acc[3]);
        red[c][tid & 31] = v;
        __syncthreads();
        if (c == 0) {
            float r = 0.f;
#pragma unroll
            for (int si = 0; si < 10; ++si) r += red[si][tid & 31];
            g_tproj[j] = r + __ldg(b1 + j);
        }
    }
}

// ---------------- 3a) h-GEMM: 128x128 tile, 8x8 microtile, split-K 9 ----------
__global__ __launch_bounds__(256) void gemm_h_k(const float* __restrict__ Wb) {
    const int z = blockIdx.z;
    const int kb = z * 288;
    const int klen = (z == 8) ? 256 : 288;
    const int NT = klen / 8;

    const int rb = blockIdx.y * 128, cb = blockIdx.x * 128;
    const int t = threadIdx.x;
    const int alr = t >> 1, alk = (t & 1) * 4;   // A: 128 rows x 2 k-quads
    const int bk = t >> 5, bc = (t & 31) * 4;    // B: 8 k x 32 col-quads
    const int ty = t >> 4, tx = t & 15;

    const float* Ap = g_pooled + (size_t)(rb + alr) * EM + kb + alk;
    const float* Bp = Wb + (size_t)(kb + bk) * HID + cb + bc;

    __shared__ __align__(16) float As[2][8][132];
    __shared__ __align__(16) float Bs[2][8][132];

    float4 pa = *reinterpret_cast<const float4*>(Ap);
    float4 pb = *reinterpret_cast<const float4*>(Bp);
    As[0][alk + 0][alr] = pa.x;
    As[0][alk + 1][alr] = pa.y;
    As[0][alk + 2][alr] = pa.z;
    As[0][alk + 3][alr] = pa.w;
    *reinterpret_cast<float4*>(&Bs[0][bk][bc]) = pb;
    __syncthreads();

    float acc[8][8];
#pragma unroll
    for (int i = 0; i < 8; ++i)
#pragma unroll
        for (int j = 0; j < 8; ++j) acc[i][j] = 0.f;

    for (int kt = 0; kt < NT; ++kt) {
        const int buf = kt & 1;
        if (kt + 1 < NT) {
            pa = *reinterpret_cast<const float4*>(Ap + (kt + 1) * 8);
            pb = *reinterpret_cast<const float4*>(Bp + (size_t)(kt + 1) * 8 * HID);
        }
#pragma unroll
        for (int kk = 0; kk < 8; ++kk) {
            float4 a0 = *reinterpret_cast<const float4*>(&As[buf][kk][ty * 8]);
            float4 a1 = *reinterpret_cast<const float4*>(&As[buf][kk][ty * 8 + 4]);
            float4 b0 = *reinterpret_cast<const float4*>(&Bs[buf][kk][tx * 8]);
            float4 b1 = *reinterpret_cast<const float4*>(&Bs[buf][kk][tx * 8 + 4]);
            float ar[8] = {a0.x, a0.y, a0.z, a0.w, a1.x, a1.y, a1.z, a1.w};
            float br[8] = {b0.x, b0.y, b0.z, b0.w, b1.x, b1.y, b1.z, b1.w};
#pragma unroll
            for (int i = 0; i < 8; ++i)
#pragma unroll
                for (int j = 0; j < 8; ++j) acc[i][j] += ar[i] * br[j];
        }
        if (kt + 1 < NT) {
            const int nb = buf ^ 1;
            As[nb][alk + 0][alr] = pa.x;
            As[nb][alk + 1][alr] = pa.y;
            As[nb][alk + 2][alr] = pa.z;
            As[nb][alk + 3][alr] = pa.w;
            *reinterpret_cast<float4*>(&Bs[nb][bk][bc]) = pb;
            __syncthreads();
        }
    }

    float* C = g_hp + (size_t)z * NF * HID;
#pragma unroll
    for (int i = 0; i < 8; ++i) {
        float* cp = C + (size_t)(rb + ty * 8 + i) * HID + cb + tx * 8;
        *reinterpret_cast<float4*>(cp) =
            make_float4(acc[i][0], acc[i][1], acc[i][2], acc[i][3]);
        *reinterpret_cast<float4*>(cp + 4) =
            make_float4(acc[i][4], acc[i][5], acc[i][6], acc[i][7]);
    }
}

// ---------------- 3b) f2f GEMM (top-64 rows), 64x64 tile ----------------------
__global__ __launch_bounds__(256) void gemm_f2f_k() {
    constexpr int KCH = EM / KS_F;
    constexpr int NT  = KCH / 16;

    const float* __restrict__ A = g_pooled;
    const float* __restrict__ B = g_pooled;
    float* __restrict__ C = g_fp + (size_t)blockIdx.z * NTOP * NF;

    const int rb = blockIdx.y * 64, cb = blockIdx.x * 64;
    const int kb = blockIdx.z * KCH;
    const int t  = threadIdx.x;
    const int lr = t >> 2, lk = (t & 3) * 4;
    const int ty = t >> 4, tx = t & 15;

    const int arow = g_order[rb + lr];
    const float* Ap = A + (size_t)arow * EM + kb + lk;
    const float* Bp = B + (size_t)(cb + lr) * EM + kb + lk;

    __shared__ __align__(16) float As[2][16][68];
    __shared__ __align__(16) float Bs[2][16][68];

    float4 pa = *reinterpret_cast<const float4*>(Ap);
    float4 pb = *reinterpret_cast<const float4*>(Bp);
    As[0][lk + 0][lr] = pa.x;
    As[0][lk + 1][lr] = pa.y;
    As[0][lk + 2][lr] = pa.z;
    As[0][lk + 3][lr] = pa.w;
    Bs[0][lk + 0][lr] = pb.x;
    Bs[0][lk + 1][lr] = pb.y;
    Bs[0][lk + 2][lr] = pb.z;
    Bs[0][lk + 3][lr] = pb.w;
    __syncthreads();

    float acc[4][4];
#pragma unroll
    for (int i = 0; i < 4; ++i)
#pragma unroll
        for (int j = 0; j < 4; ++j) acc[i][j] = 0.f;

    for (int kt = 0; kt < NT; ++kt) {
        const int buf = kt & 1;
        if (kt + 1 < NT) {
            pa = *reinterpret_cast<const float4*>(Ap + (kt + 1) * 16);
            pb = *reinterpret_cast<const float4*>(Bp + (kt + 1) * 16);
        }
#pragma unroll
        for (int kk = 0; kk < 16; ++kk) {
            float4 av = *reinterpret_cast<const float4*>(&As[buf][kk][ty * 4]);
            float4 bv = *reinterpret_cast<const float4*>(&Bs[buf][kk][tx * 4]);
            float ar[4] = {av.x, av.y, av.z, av.w};
            float br[4] = {bv.x, bv.y, bv.z, bv.w};
#pragma unroll
            for (int i = 0; i < 4; ++i)
#pragma unroll
                for (int j = 0; j < 4; ++j) acc[i][j] += ar[i] * br[j];
        }
        if (kt + 1 < NT) {
            const int nb = buf ^ 1;
            As[nb][lk + 0][lr] = pa.x;
            As[nb][lk + 1][lr] = pa.y;
            As[nb][lk + 2][lr] = pa.z;
            As[nb][lk + 3][lr] = pa.w;
            Bs[nb][lk + 0][lr] = pb.x;
            Bs[nb][lk + 1][lr] = pb.y;
            Bs[nb][lk + 2][lr] = pb.z;
            Bs[nb][lk + 3][lr] = pb.w;
            __syncthreads();
        }
    }

    float rs[4], cs[4];
#pragma unroll
    for (int r = 0; r < 4; ++r) rs[r] = g_invn[g_order[rb + ty * 4 + r]];
#pragma unroll
    for (int j = 0; j < 4; ++j) cs[j] = g_invn[cb + tx * 4 + j];
#pragma unroll
    for (int i = 0; i < 4; ++i) {
        float4 v = make_float4(acc[i][0] * rs[i] * cs[0], acc[i][1] * rs[i] * cs[1],
                               acc[i][2] * rs[i] * cs[2], acc[i][3] * rs[i] * cs[3]);
        *reinterpret_cast<float4*>(C + (size_t)(rb + ty * 4 + i) * 512 + cb + tx * 4) = v;
    }
}

// ---------------- 4) gates: sigmoid(relu(h_sum + tproj) @ W2 + b2) ------------
__global__ __launch_bounds__(128) void gates_k(
    const float* __restrict__ W2, const float* __restrict__ b2) {
    const int n = blockIdx.x, tid = threadIdx.x;   // tid = float4 column
    float4 hv = *(reinterpret_cast<const float4*>(g_tproj) + tid);
#pragma unroll
    for (int s = 0; s < KS_H; ++s) {
        float4 p = *(reinterpret_cast<const float4*>(g_hp + (size_t)s * NF * HID + (size_t)n * HID) + tid);
        hv.x += p.x; hv.y += p.y; hv.z += p.z; hv.w += p.w;
    }
    const float4 w = __ldg(reinterpret_cast<const float4*>(W2) + tid);
    float v = fmaxf(hv.x, 0.f) * w.x + fmaxf(hv.y, 0.f) * w.y
            + fmaxf(hv.z, 0.f) * w.z + fmaxf(hv.w, 0.f) * w.w;
    __shared__ float sm[4];
    int lane = tid & 31, wid = tid >> 5;
#pragma unroll
    for (int o = 16; o > 0; o >>= 1) v += __shfl_down_sync(0xffffffffu, v, o);
    if (lane == 0) sm[wid] = v;
    __syncthreads();
    if (tid == 0) {
        float z = sm[0] + sm[1] + sm[2] + sm[3] + __ldg(b2);
        g_gates[n] = 1.0f / (1.0f + expf(-z));
    }
}

// ---------------- 5) stable descending rank-sort ------------------------------
__global__ __launch_bounds__(NF) void sort_k() {
    __shared__ unsigned long long keys[NF];
    const int i = threadIdx.x;
    unsigned int bits = __float_as_uint(g_gates[i]);
    keys[i] = ((unsigned long long)(0xFFFFFFFFu - bits) << 32) | (unsigned int)i;
    __syncthreads();
    const unsigned long long me = keys[i];
    int r = 0;
    for (int j = 0; j < NF; ++j) r += (keys[j] < me) ? 1 : 0;
    g_order[r] = i;
}

// ---------------- 6) reduce f2f partials -> similarity bitmask ----------------
__global__ __launch_bounds__(128) void mask_k() {
    const int r = blockIdx.x, t = threadIdx.x;
    float4 s = *(reinterpret_cast<const float4*>(g_fp + (size_t)r * NF) + t);
#pragma unroll
    for (int sp = 1; sp < KS_F; ++sp) {
        float4 p = *(reinterpret_cast<const float4*>(g_fp + (size_t)sp * NTOP * NF + (size_t)r * NF) + t);
        s.x += p.x; s.y += p.y; s.z += p.z; s.w += p.w;
    }
    __shared__ unsigned char nib[128];
    unsigned int n = (s.x > 0.98f ? 1u : 0u) | (s.y > 0.98f ? 2u : 0u)
                   | (s.z > 0.98f ? 4u : 0u) | (s.w > 0.98f ? 8u : 0u);
    nib[t] = (unsigned char)n;
    __syncthreads();
    if (t < 16) {
        unsigned int w = 0;
#pragma unroll
        for (int b = 0; b < 8; ++b) w |= ((unsigned int)nib[8 * t + b]) << (4 * b);
        g_mask[r * 16 + t] = w;
    }
}

// ---------------- 7) greedy selection scan + output ---------------------------
__global__ __launch_bounds__(NF) void scan_k(float* __restrict__ out) {
    __shared__ int s_count, s_done, s_cur, s_take;
    __shared__ unsigned char vis[NF], sel[NF];
    __shared__ unsigned int msk[NTOP * 16];
    const int tid = threadIdx.x;
    vis[tid] = 0;
    sel[tid] = 0;
    if (tid == 0) { s_count = 0; s_done = 0; }
    msk[tid] = g_mask[tid];
    msk[tid + 512] = g_mask[tid + 512];
    __syncthreads();
    for (int pos = 0; pos < NF; ++pos) {
        if (tid == 0) {
            if (s_count >= 32) {
                s_done = 1;
            } else {
                int cur = g_order[pos];
                s_cur = cur;
                int take = vis[cur] ? 0 : 1;
                s_take = take;
                if (take) { sel[cur] = 1; s_count++; }
            }
        }
        __syncthreads();
        if (s_done) break;
        if (s_take) {
            bool hit;
            if (pos < NTOP) {
                hit = (msk[pos * 16 + (tid >> 5)] >> (tid & 31)) & 1u;
            } else {                               // exact fallback (not hit on normal data)
                const float* a = g_pooled + (size_t)s_cur * EM;
                const float* bb = g_pooled + (size_t)tid * EM;
                float d = 0.f;
                for (int e = 0; e < EM; ++e) d += a[e] * bb[e];
                hit = d * g_invn[s_cur] * g_invn[tid] > 0.98f;
            }
            if (hit) vis[tid] = 1;
        }
        __syncthreads();
    }
    __syncthreads();
    out[tid] = (float)sel[tid];
    out[NF + tid] = g_gates[tid];
}

// ---------------- launch ------------------------------------------------------
extern "C" void kernel_launch(void* const* d_in, const int* in_sizes, int n_in,
                              void* d_out, int out_size) {
    const float* img    = (const float*)d_in[0];
    const float* txt    = (const float*)d_in[1];
    const float* ln_t_g = (const float*)d_in[2];
    const float* ln_t_b = (const float*)d_in[3];
    const float* ln_l_g = (const float*)d_in[4];
    const float* ln_l_b = (const float*)d_in[5];
    const float* W1     = (const float*)d_in[6];
    const float* b1     = (const float*)d_in[7];
    const float* W2     = (const float*)d_in[8];
    const float* b2     = (const float*)d_in[9];
    float* out = (float*)d_out;

    pool_tproj_k<<<NF + 16, POOL_T>>>(img, ln_l_g, ln_l_b,
                                      txt, ln_t_g, ln_t_b, W1, b1);
    gemm_h_k<<<dim3(4, 4, KS_H), 256>>>(W1 + (size_t)EM * HID);
    gates_k<<<NF, 128>>>(W2, b2);
    sort_k<<<1, NF>>>();
    gemm_f2f_k<<<dim3(8, 1, KS_F), 256>>>();
    mask_k<<<NTOP, 128>>>();
    scan_k<<<1, NF>>>(out);
}

// round 10
// speedup vs baseline: 1.2010x; 1.0253x over previous
#include <cuda_runtime.h>
#include <math.h>

#define NF   512
#define TK   196
#define EM   2560
#define HID  512
#define E4   (EM/4)
#define POOL_T 320
#define NTOP 64
#define KS_H 9
#define KS_F 16

// ---------------- scratch (static device globals) ----------------------------
__device__ float g_pooled[NF * EM];         // layer-normed pooled features
__device__ float g_invn[NF];                // 1/||pooled_ln|| per frame
__device__ float g_tproj[HID];              // txt_ln @ W1_top + b1
__device__ float g_hp[KS_H * NF * HID];     // split-K partials of pooled_ln @ W1_bot
__device__ float g_fp[KS_F * NTOP * NF];    // split-K partials of top-64 f2f rows
__device__ float g_gates[NF];
__device__ int   g_order[NF];
__device__ unsigned int g_mask[NTOP * 16];  // f2f>0.98 bitmask for top-64 rows

// ---------------- block reduce of two scalars --------------------------------
__device__ __forceinline__ void blk_reduce2(float& a, float& b, float* sm, int nwarp) {
    int lane = threadIdx.x & 31, wid = threadIdx.x >> 5;
#pragma unroll
    for (int o = 16; o > 0; o >>= 1) {
        a += __shfl_down_sync(0xffffffffu, a, o);
        b += __shfl_down_sync(0xffffffffu, b, o);
    }
    if (lane == 0) { sm[wid] = a; sm[wid + 16] = b; }
    __syncthreads();
    if (wid == 0) {
        a = lane < nwarp ? sm[lane] : 0.f;
        b = lane < nwarp ? sm[lane + 16] : 0.f;
#pragma unroll
        for (int o = 16; o > 0; o >>= 1) {
            a += __shfl_down_sync(0xffffffffu, a, o);
            b += __shfl_down_sync(0xffffffffu, b, o);
        }
        if (lane == 0) { sm[32] = a; sm[33] = b; }
    }
    __syncthreads();
    a = sm[32];
    b = sm[33];
    __syncthreads();
}

// ---------------- 1) pool+LN (blocks 0..511) / txt-LN+proj (blocks 512..527) --
__global__ __launch_bounds__(POOL_T) void pool_tproj_k(
    const float* __restrict__ img, const float* __restrict__ g,
    const float* __restrict__ b,
    const float* __restrict__ xt, const float* __restrict__ gt,
    const float* __restrict__ bt, const float* __restrict__ W1,
    const float* __restrict__ b1) {
    const int tid = threadIdx.x;

    if (blockIdx.x < NF) {
        const int f = blockIdx.x;
        const float4* base = reinterpret_cast<const float4*>(img) + (size_t)f * TK * E4;
        const int c0 = tid, c1 = tid + POOL_T;

        float4 a0 = make_float4(0.f, 0.f, 0.f, 0.f);
        float4 a1 = make_float4(0.f, 0.f, 0.f, 0.f);
        for (int t = 0; t < TK; t += 4) {           // 196 = 49*4, MLP=8
            float4 v[8];
#pragma unroll
            for (int u = 0; u < 4; ++u) {
                v[2 * u]     = __ldcs(base + (size_t)(t + u) * E4 + c0);
                v[2 * u + 1] = __ldcs(base + (size_t)(t + u) * E4 + c1);
            }
#pragma unroll
            for (int u = 0; u < 4; ++u) {
                a0.x += v[2*u].x;   a0.y += v[2*u].y;   a0.z += v[2*u].z;   a0.w += v[2*u].w;
                a1.x += v[2*u+1].x; a1.y += v[2*u+1].y; a1.z += v[2*u+1].z; a1.w += v[2*u+1].w;
            }
        }
        const float inv = 1.0f / (float)TK;
        a0.x *= inv; a0.y *= inv; a0.z *= inv; a0.w *= inv;
        a1.x *= inv; a1.y *= inv; a1.z *= inv; a1.w *= inv;

        float s = a0.x + a0.y + a0.z + a0.w + a1.x + a1.y + a1.z + a1.w;
        float q = a0.x*a0.x + a0.y*a0.y + a0.z*a0.z + a0.w*a0.w
                + a1.x*a1.x + a1.y*a1.y + a1.z*a1.z + a1.w*a1.w;

        __shared__ float sm[34];
        blk_reduce2(s, q, sm, POOL_T / 32);
        const float mean = s / (float)EM;
        const float var  = q / (float)EM - mean * mean;
        const float rstd = rsqrtf(var + 1e-5f);

        const float4 g0 = __ldg(reinterpret_cast<const float4*>(g) + c0);
        const float4 g1 = __ldg(reinterpret_cast<const float4*>(g) + c1);
        const float4 b0 = __ldg(reinterpret_cast<const float4*>(b) + c0);
        const float4 b1v = __ldg(reinterpret_cast<const float4*>(b) + c1);

        float4 y0, y1;
        y0.x = (a0.x - mean) * rstd * g0.x + b0.x;
        y0.y = (a0.y - mean) * rstd * g0.y + b0.y;
        y0.z = (a0.z - mean) * rstd * g0.z + b0.z;
        y0.w = (a0.w - mean) * rstd * g0.w + b0.w;
        y1.x = (a1.x - mean) * rstd * g1.x + b1v.x;
        y1.y = (a1.y - mean) * rstd * g1.y + b1v.y;
        y1.z = (a1.z - mean) * rstd * g1.z + b1v.z;
        y1.w = (a1.w - mean) * rstd * g1.w + b1v.w;

        float4* pooled4 = reinterpret_cast<float4*>(g_pooled) + (size_t)f * E4;
        pooled4[c0] = y0;
        pooled4[c1] = y1;

        float q2 = y0.x*y0.x + y0.y*y0.y + y0.z*y0.z + y0.w*y0.w
                 + y1.x*y1.x + y1.y*y1.y + y1.z*y1.z + y1.w*y1.w;
        float dummy = 0.f;
        blk_reduce2(q2, dummy, sm, POOL_T / 32);
        if (tid == 0) g_invn[f] = 1.0f / fmaxf(sqrtf(q2), 1e-8f);
    } else {
        __shared__ float st[EM];
        __shared__ float smt[34];
        __shared__ float red[10][33];
        const int blk = blockIdx.x - NF;            // 0..15
        float xs[8];
        float s = 0.f, q = 0.f;
#pragma unroll
        for (int k = 0; k < 8; ++k) {               // 320*8 = 2560
            int e = tid + k * POOL_T;
            xs[k] = __ldg(xt + e);
            s += xs[k];
            q += xs[k] * xs[k];
        }
        blk_reduce2(s, q, smt, POOL_T / 32);
        const float mean = s / (float)EM;
        const float var  = q / (float)EM - mean * mean;
        const float rstd = rsqrtf(var + 1e-5f);
#pragma unroll
        for (int k = 0; k < 8; ++k) {
            int e = tid + k * POOL_T;
            st[e] = (xs[k] - mean) * rstd * __ldg(gt + e) + __ldg(bt + e);
        }
        __syncthreads();

        const int j = blk * 32 + (tid & 31);
        const int c = tid >> 5;                     // 10 warps, 256-elem K-chunks
        const float* wp = W1 + (size_t)(c * 256) * HID + j;
        float acc[4] = {0.f, 0.f, 0.f, 0.f};
        for (int e = 0; e < 256; e += 4) {
#pragma unroll
            for (int u = 0; u < 4; ++u)
                acc[u] += st[c * 256 + e + u] * __ldg(wp + (size_t)(e + u) * HID);
        }
        float v = (acc[0] + acc[1]) + (acc[2] + acc[3]);
        red[c][tid & 31] = v;
        __syncthreads();
        if (c == 0) {
            float r = 0.f;
#pragma unroll
            for (int si = 0; si < 10; ++si) r += red[si][tid & 31];
            g_tproj[j] = r + __ldg(b1 + j);
        }
    }
}

// ---------------- 3a) h-GEMM: 128x128 tile, 8x8 microtile, split-K 9 ----------
__global__ __launch_bounds__(256) void gemm_h_k(const float* __restrict__ Wb) {
    const int z = blockIdx.z;
    const int kb = z * 288;
    const int klen = (z == 8) ? 256 : 288;
    const int NT = klen / 8;

    const int rb = blockIdx.y * 128, cb = blockIdx.x * 128;
    const int t = threadIdx.x;
    const int alr = t >> 1, alk = (t & 1) * 4;   // A: 128 rows x 2 k-quads
    const int bk = t >> 5, bc = (t & 31) * 4;    // B: 8 k x 32 col-quads
    const int ty = t >> 4, tx = t & 15;

    const float* Ap = g_pooled + (size_t)(rb + alr) * EM + kb + alk;
    const float* Bp = Wb + (size_t)(kb + bk) * HID + cb + bc;

    __shared__ __align__(16) float As[2][8][132];
    __shared__ __align__(16) float Bs[2][8][132];

    float4 pa = *reinterpret_cast<const float4*>(Ap);
    float4 pb = *reinterpret_cast<const float4*>(Bp);
    As[0][alk + 0][alr] = pa.x;
    As[0][alk + 1][alr] = pa.y;
    As[0][alk + 2][alr] = pa.z;
    As[0][alk + 3][alr] = pa.w;
    *reinterpret_cast<float4*>(&Bs[0][bk][bc]) = pb;
    __syncthreads();

    float acc[8][8];
#pragma unroll
    for (int i = 0; i < 8; ++i)
#pragma unroll
        for (int j = 0; j < 8; ++j) acc[i][j] = 0.f;

    for (int kt = 0; kt < NT; ++kt) {
        const int buf = kt & 1;
        if (kt + 1 < NT) {
            pa = *reinterpret_cast<const float4*>(Ap + (kt + 1) * 8);
            pb = *reinterpret_cast<const float4*>(Bp + (size_t)(kt + 1) * 8 * HID);
        }
#pragma unroll
        for (int kk = 0; kk < 8; ++kk) {
            float4 a0 = *reinterpret_cast<const float4*>(&As[buf][kk][ty * 8]);
            float4 a1 = *reinterpret_cast<const float4*>(&As[buf][kk][ty * 8 + 4]);
            float4 b0 = *reinterpret_cast<const float4*>(&Bs[buf][kk][tx * 8]);
            float4 b1 = *reinterpret_cast<const float4*>(&Bs[buf][kk][tx * 8 + 4]);
            float ar[8] = {a0.x, a0.y, a0.z, a0.w, a1.x, a1.y, a1.z, a1.w};
            float br[8] = {b0.x, b0.y, b0.z, b0.w, b1.x, b1.y, b1.z, b1.w};
#pragma unroll
            for (int i = 0; i < 8; ++i)
#pragma unroll
                for (int j = 0; j < 8; ++j) acc[i][j] += ar[i] * br[j];
        }
        if (kt + 1 < NT) {
            const int nb = buf ^ 1;
            As[nb][alk + 0][alr] = pa.x;
            As[nb][alk + 1][alr] = pa.y;
            As[nb][alk + 2][alr] = pa.z;
            As[nb][alk + 3][alr] = pa.w;
            *reinterpret_cast<float4*>(&Bs[nb][bk][bc]) = pb;
            __syncthreads();
        }
    }

    float* C = g_hp + (size_t)z * NF * HID;
#pragma unroll
    for (int i = 0; i < 8; ++i) {
        float* cp = C + (size_t)(rb + ty * 8 + i) * HID + cb + tx * 8;
        *reinterpret_cast<float4*>(cp) =
            make_float4(acc[i][0], acc[i][1], acc[i][2], acc[i][3]);
        *reinterpret_cast<float4*>(cp + 4) =
            make_float4(acc[i][4], acc[i][5], acc[i][6], acc[i][7]);
    }
}

// ---------------- 3b) f2f GEMM (top-64 rows), 64x64 tile, split-K 16 ----------
__global__ __launch_bounds__(256) void gemm_f2f_k() {
    constexpr int KCH = EM / KS_F;               // 160
    constexpr int NT  = KCH / 16;                // 10

    const float* __restrict__ A = g_pooled;
    const float* __restrict__ B = g_pooled;
    float* __restrict__ C = g_fp + (size_t)blockIdx.z * NTOP * NF;

    const int rb = blockIdx.y * 64, cb = blockIdx.x * 64;
    const int kb = blockIdx.z * KCH;
    const int t  = threadIdx.x;
    const int lr = t >> 2, lk = (t & 3) * 4;
    const int ty = t >> 4, tx = t & 15;

    const int arow = g_order[rb + lr];
    const float* Ap = A + (size_t)arow * EM + kb + lk;
    const float* Bp = B + (size_t)(cb + lr) * EM + kb + lk;

    __shared__ __align__(16) float As[2][16][68];
    __shared__ __align__(16) float Bs[2][16][68];

    float4 pa = *reinterpret_cast<const float4*>(Ap);
    float4 pb = *reinterpret_cast<const float4*>(Bp);
    As[0][lk + 0][lr] = pa.x;
    As[0][lk + 1][lr] = pa.y;
    As[0][lk + 2][lr] = pa.z;
    As[0][lk + 3][lr] = pa.w;
    Bs[0][lk + 0][lr] = pb.x;
    Bs[0][lk + 1][lr] = pb.y;
    Bs[0][lk + 2][lr] = pb.z;
    Bs[0][lk + 3][lr] = pb.w;
    __syncthreads();

    float acc[4][4];
#pragma unroll
    for (int i = 0; i < 4; ++i)
#pragma unroll
        for (int j = 0; j < 4; ++j) acc[i][j] = 0.f;

    for (int kt = 0; kt < NT; ++kt) {
        const int buf = kt & 1;
        if (kt + 1 < NT) {
            pa = *reinterpret_cast<const float4*>(Ap + (kt + 1) * 16);
            pb = *reinterpret_cast<const float4*>(Bp + (kt + 1) * 16);
        }
#pragma unroll
        for (int kk = 0; kk < 16; ++kk) {
            float4 av = *reinterpret_cast<const float4*>(&As[buf][kk][ty * 4]);
            float4 bv = *reinterpret_cast<const float4*>(&Bs[buf][kk][tx * 4]);
            float ar[4] = {av.x, av.y, av.z, av.w};
            float br[4] = {bv.x, bv.y, bv.z, bv.w};
#pragma unroll
            for (int i = 0; i < 4; ++i)
#pragma unroll
                for (int j = 0; j < 4; ++j) acc[i][j] += ar[i] * br[j];
        }
        if (kt + 1 < NT) {
            const int nb = buf ^ 1;
            As[nb][lk + 0][lr] = pa.x;
            As[nb][lk + 1][lr] = pa.y;
            As[nb][lk + 2][lr] = pa.z;
            As[nb][lk + 3][lr] = pa.w;
            Bs[nb][lk + 0][lr] = pb.x;
            Bs[nb][lk + 1][lr] = pb.y;
            Bs[nb][lk + 2][lr] = pb.z;
            Bs[nb][lk + 3][lr] = pb.w;
            __syncthreads();
        }
    }

    float rs[4], cs[4];
#pragma unroll
    for (int r = 0; r < 4; ++r) rs[r] = g_invn[g_order[rb + ty * 4 + r]];
#pragma unroll
    for (int j = 0; j < 4; ++j) cs[j] = g_invn[cb + tx * 4 + j];
#pragma unroll
    for (int i = 0; i < 4; ++i) {
        float4 v = make_float4(acc[i][0] * rs[i] * cs[0], acc[i][1] * rs[i] * cs[1],
                               acc[i][2] * rs[i] * cs[2], acc[i][3] * rs[i] * cs[3]);
        *reinterpret_cast<float4*>(C + (size_t)(rb + ty * 4 + i) * 512 + cb + tx * 4) = v;
    }
}

// ---------------- 4) gates: sigmoid(relu(h_sum + tproj) @ W2 + b2) ------------
__global__ __launch_bounds__(128) void gates_k(
    const float* __restrict__ W2, const float* __restrict__ b2) {
    const int n = blockIdx.x, tid = threadIdx.x;   // tid = float4 column
    float4 hv = *(reinterpret_cast<const float4*>(g_tproj) + tid);
#pragma unroll
    for (int s = 0; s < KS_H; ++s) {
        float4 p = *(reinterpret_cast<const float4*>(g_hp + (size_t)s * NF * HID + (size_t)n * HID) + tid);
        hv.x += p.x; hv.y += p.y; hv.z += p.z; hv.w += p.w;
    }
    const float4 w = __ldg(reinterpret_cast<const float4*>(W2) + tid);
    float v = fmaxf(hv.x, 0.f) * w.x + fmaxf(hv.y, 0.f) * w.y
            + fmaxf(hv.z, 0.f) * w.z + fmaxf(hv.w, 0.f) * w.w;
    __shared__ float sm[4];
    int lane = tid & 31, wid = tid >> 5;
#pragma unroll
    for (int o = 16; o > 0; o >>= 1) v += __shfl_down_sync(0xffffffffu, v, o);
    if (lane == 0) sm[wid] = v;
    __syncthreads();
    if (tid == 0) {
        float z = sm[0] + sm[1] + sm[2] + sm[3] + __ldg(b2);
        g_gates[n] = 1.0f / (1.0f + expf(-z));
    }
}

// ---------------- 5) stable descending rank-sort (2 threads per key) ----------
__global__ __launch_bounds__(1024) void sort_k() {
    __shared__ unsigned long long keys[NF];
    __shared__ unsigned short pr[NF];
    const int t = threadIdx.x;
    const int i = t & 511, half = t >> 9;
    if (half == 0) {
        unsigned int bits = __float_as_uint(g_gates[i]);  // sigmoid>0 -> monotone bits
        keys[i] = ((unsigned long long)(0xFFFFFFFFu - bits) << 32) | (unsigned int)i;
    }
    __syncthreads();
    const unsigned long long me = keys[i];
    const int j0 = half * 256;
    int r = 0;
#pragma unroll 8
    for (int j = 0; j < 256; ++j) r += (keys[j0 + j] < me) ? 1 : 0;
    if (half == 1) pr[i] = (unsigned short)r;
    __syncthreads();
    if (half == 0) g_order[r + (int)pr[i]] = i;
}

// ---------------- 6) reduce f2f partials -> similarity bitmask ----------------
__global__ __launch_bounds__(128) void mask_k() {
    const int r = blockIdx.x, t = threadIdx.x;
    float4 s = *(reinterpret_cast<const float4*>(g_fp + (size_t)r * NF) + t);
#pragma unroll
    for (int sp = 1; sp < KS_F; ++sp) {
        float4 p = *(reinterpret_cast<const float4*>(g_fp + (size_t)sp * NTOP * NF + (size_t)r * NF) + t);
        s.x += p.x; s.y += p.y; s.z += p.z; s.w += p.w;
    }
    __shared__ unsigned char nib[128];
    unsigned int n = (s.x > 0.98f ? 1u : 0u) | (s.y > 0.98f ? 2u : 0u)
                   | (s.z > 0.98f ? 4u : 0u) | (s.w > 0.98f ? 8u : 0u);
    nib[t] = (unsigned char)n;
    __syncthreads();
    if (t < 16) {
        unsigned int w = 0;
#pragma unroll
        for (int b = 0; b < 8; ++b) w |= ((unsigned int)nib[8 * t + b]) << (4 * b);
        g_mask[r * 16 + t] = w;
    }
}

// ---------------- 7) greedy selection scan + output ---------------------------
__global__ __launch_bounds__(NF) void scan_k(float* __restrict__ out) {
    __shared__ int s_count, s_done, s_cur, s_take;
    __shared__ unsigned char vis[NF], sel[NF];
    __shared__ unsigned int msk[NTOP * 16];
    const int tid = threadIdx.x;
    vis[tid] = 0;
    sel[tid] = 0;
    if (tid == 0) { s_count = 0; s_done = 0; }
    msk[tid] = g_mask[tid];
    msk[tid + 512] = g_mask[tid + 512];
    __syncthreads();
    for (int pos = 0; pos < NF; ++pos) {
        if (tid == 0) {
            if (s_count >= 32) {
                s_done = 1;
            } else {
                int cur = g_order[pos];
                s_cur = cur;
                int take = vis[cur] ? 0 : 1;
                s_take = take;
                if (take) { sel[cur] = 1; s_count++; }
            }
        }
        __syncthreads();
        if (s_done) break;
        if (s_take) {
            bool hit;
            if (pos < NTOP) {
                hit = (msk[pos * 16 + (tid >> 5)] >> (tid & 31)) & 1u;
            } else {                               // exact fallback (not hit on normal data)
                const float* a = g_pooled + (size_t)s_cur * EM;
                const float* bb = g_pooled + (size_t)tid * EM;
                float d = 0.f;
                for (int e = 0; e < EM; ++e) d += a[e] * bb[e];
                hit = d * g_invn[s_cur] * g_invn[tid] > 0.98f;
            }
            if (hit) vis[tid] = 1;
        }
        __syncthreads();
    }
    __syncthreads();
    out[tid] = (float)sel[tid];
    out[NF + tid] = g_gates[tid];
}

// ---------------- launch ------------------------------------------------------
extern "C" void kernel_launch(void* const* d_in, const int* in_sizes, int n_in,
                              void* d_out, int out_size) {
    const float* img    = (const float*)d_in[0];
    const float* txt    = (const float*)d_in[1];
    const float* ln_t_g = (const float*)d_in[2];
    const float* ln_t_b = (const float*)d_in[3];
    const float* ln_l_g = (const float*)d_in[4];
    const float* ln_l_b = (const float*)d_in[5];
    const float* W1     = (const float*)d_in[6];
    const float* b1     = (const float*)d_in[7];
    const float* W2     = (const float*)d_in[8];
    const float* b2     = (const float*)d_in[9];
    float* out = (float*)d_out;

    pool_tproj_k<<<NF + 16, POOL_T>>>(img, ln_l_g, ln_l_b,
                                      txt, ln_t_g, ln_t_b, W1, b1);
    gemm_h_k<<<dim3(4, 4, KS_H), 256>>>(W1 + (size_t)EM * HID);
    gates_k<<<NF, 128>>>(W2, b2);
    sort_k<<<1, 1024>>>();
    gemm_f2f_k<<<dim3(8, 1, KS_F), 256>>>();
    mask_k<<<NTOP, 128>>>();
    scan_k<<<1, NF>>>(out);
}

// round 14
// speedup vs baseline: 1.2048x; 1.0032x over previous
#include <cuda_runtime.h>
#include <math.h>

#define NF   512
#define TK   196
#define EM   2560
#define HID  512
#define E4   (EM/4)
#define POOL_T 320
#define NTOP 64
#define KS_H 9
#define KS_F 16

// ---------------- scratch (static device globals) ----------------------------
__device__ float g_pooled[NF * EM];         // layer-normed pooled features
__device__ float g_invn[NF];                // 1/||pooled_ln|| per frame
__device__ float g_tproj[HID];              // txt_ln @ W1_top + b1
__device__ float g_hp[KS_H * NF * HID];     // split-K partials of pooled_ln @ W1_bot
__device__ float g_fp[KS_F * NTOP * NF];    // split-K partials of top-64 f2f rows
__device__ float g_gates[NF];
__device__ int   g_order[NF];
__device__ unsigned int g_mask[NTOP * 16];  // f2f>0.98 bitmask for top-64 rows

// ---------------- block reduce of two scalars --------------------------------
__device__ __forceinline__ void blk_reduce2(float& a, float& b, float* sm, int nwarp) {
    int lane = threadIdx.x & 31, wid = threadIdx.x >> 5;
#pragma unroll
    for (int o = 16; o > 0; o >>= 1) {
        a += __shfl_down_sync(0xffffffffu, a, o);
        b += __shfl_down_sync(0xffffffffu, b, o);
    }
    if (lane == 0) { sm[wid] = a; sm[wid + 16] = b; }
    __syncthreads();
    if (wid == 0) {
        a = lane < nwarp ? sm[lane] : 0.f;
        b = lane < nwarp ? sm[lane + 16] : 0.f;
#pragma unroll
        for (int o = 16; o > 0; o >>= 1) {
            a += __shfl_down_sync(0xffffffffu, a, o);
            b += __shfl_down_sync(0xffffffffu, b, o);
        }
        if (lane == 0) { sm[32] = a; sm[33] = b; }
    }
    __syncthreads();
    a = sm[32];
    b = sm[33];
    __syncthreads();
}

// ---------------- 1) pool+LN (blocks 0..511) / txt-LN+proj (blocks 512..527) --
__global__ __launch_bounds__(POOL_T) void pool_tproj_k(
    const float* __restrict__ img, const float* __restrict__ g,
    const float* __restrict__ b,
    const float* __restrict__ xt, const float* __restrict__ gt,
    const float* __restrict__ bt, const float* __restrict__ W1,
    const float* __restrict__ b1) {
    const int tid = threadIdx.x;

    if (blockIdx.x < NF) {
        const int f = blockIdx.x;
        const float4* base = reinterpret_cast<const float4*>(img) + (size_t)f * TK * E4;
        const int c0 = tid, c1 = tid + POOL_T;

        float4 a0 = make_float4(0.f, 0.f, 0.f, 0.f);
        float4 a1 = make_float4(0.f, 0.f, 0.f, 0.f);
        for (int t = 0; t < TK; t += 4) {           // 196 = 49*4, MLP=8
            float4 v[8];
#pragma unroll
            for (int u = 0; u < 4; ++u) {
                v[2 * u]     = __ldcs(base + (size_t)(t + u) * E4 + c0);
                v[2 * u + 1] = __ldcs(base + (size_t)(t + u) * E4 + c1);
            }
#pragma unroll
            for (int u = 0; u < 4; ++u) {
                a0.x += v[2*u].x;   a0.y += v[2*u].y;   a0.z += v[2*u].z;   a0.w += v[2*u].w;
                a1.x += v[2*u+1].x; a1.y += v[2*u+1].y; a1.z += v[2*u+1].z; a1.w += v[2*u+1].w;
            }
        }
        const float inv = 1.0f / (float)TK;
        a0.x *= inv; a0.y *= inv; a0.z *= inv; a0.w *= inv;
        a1.x *= inv; a1.y *= inv; a1.z *= inv; a1.w *= inv;

        float s = a0.x + a0.y + a0.z + a0.w + a1.x + a1.y + a1.z + a1.w;
        float q = a0.x*a0.x + a0.y*a0.y + a0.z*a0.z + a0.w*a0.w
                + a1.x*a1.x + a1.y*a1.y + a1.z*a1.z + a1.w*a1.w;

        __shared__ float sm[34];
        blk_reduce2(s, q, sm, POOL_T / 32);
        const float mean = s / (float)EM;
        const float var  = q / (float)EM - mean * mean;
        const float rstd = rsqrtf(var + 1e-5f);

        const float4 g0 = __ldg(reinterpret_cast<const float4*>(g) + c0);
        const float4 g1 = __ldg(reinterpret_cast<const float4*>(g) + c1);
        const float4 b0 = __ldg(reinterpret_cast<const float4*>(b) + c0);
        const float4 b1v = __ldg(reinterpret_cast<const float4*>(b) + c1);

        float4 y0, y1;
        y0.x = (a0.x - mean) * rstd * g0.x + b0.x;
        y0.y = (a0.y - mean) * rstd * g0.y + b0.y;
        y0.z = (a0.z - mean) * rstd * g0.z + b0.z;
        y0.w = (a0.w - mean) * rstd * g0.w + b0.w;
        y1.x = (a1.x - mean) * rstd * g1.x + b1v.x;
        y1.y = (a1.y - mean) * rstd * g1.y + b1v.y;
        y1.z = (a1.z - mean) * rstd * g1.z + b1v.z;
        y1.w = (a1.w - mean) * rstd * g1.w + b1v.w;

        float4* pooled4 = reinterpret_cast<float4*>(g_pooled) + (size_t)f * E4;
        pooled4[c0] = y0;
        pooled4[c1] = y1;

        float q2 = y0.x*y0.x + y0.y*y0.y + y0.z*y0.z + y0.w*y0.w
                 + y1.x*y1.x + y1.y*y1.y + y1.z*y1.z + y1.w*y1.w;
        float dummy = 0.f;
        blk_reduce2(q2, dummy, sm, POOL_T / 32);
        if (tid == 0) g_invn[f] = 1.0f / fmaxf(sqrtf(q2), 1e-8f);
    } else {
        __shared__ float st[EM];
        __shared__ float smt[34];
        __shared__ float red[10][33];
        const int blk = blockIdx.x - NF;            // 0..15
        float xs[8];
        float s = 0.f, q = 0.f;
#pragma unroll
        for (int k = 0; k < 8; ++k) {               // 320*8 = 2560
            int e = tid + k * POOL_T;
            xs[k] = __ldg(xt + e);
            s += xs[k];
            q += xs[k] * xs[k];
        }
        blk_reduce2(s, q, smt, POOL_T / 32);
        const float mean = s / (float)EM;
        const float var  = q / (float)EM - mean * mean;
        const float rstd = rsqrtf(var + 1e-5f);
#pragma unroll
        for (int k = 0; k < 8; ++k) {
            int e = tid + k * POOL_T;
            st[e] = (xs[k] - mean) * rstd * __ldg(gt + e) + __ldg(bt + e);
        }
        __syncthreads();

        const int j = blk * 32 + (tid & 31);
        const int c = tid >> 5;                     // 10 warps, 256-elem K-chunks
        const float* wp = W1 + (size_t)(c * 256) * HID + j;
        float acc[4] = {0.f, 0.f, 0.f, 0.f};
        for (int e = 0; e < 256; e += 4) {
#pragma unroll
            for (int u = 0; u < 4; ++u)
                acc[u] += st[c * 256 + e + u] * __ldg(wp + (size_t)(e + u) * HID);
        }
        float v = (acc[0] + acc[1]) + (acc[2] + acc[3]);
        red[c][tid & 31] = v;
        __syncthreads();
        if (c == 0) {
            float r = 0.f;
#pragma unroll
            for (int si = 0; si < 10; ++si) r += red[si][tid & 31];
            g_tproj[j] = r + __ldg(b1 + j);
        }
    }
}

// ---------------- 3a) h-GEMM: 128x128 tile, 8x8 microtile, split-K 9 ----------
__global__ __launch_bounds__(256) void gemm_h_k(const float* __restrict__ Wb) {
    const int z = blockIdx.z;
    const int kb = z * 288;
    const int klen = (z == 8) ? 256 : 288;
    const int NT = klen / 8;

    const int rb = blockIdx.y * 128, cb = blockIdx.x * 128;
    const int t = threadIdx.x;
    const int alr = t >> 1, alk = (t & 1) * 4;   // A: 128 rows x 2 k-quads
    const int bk = t >> 5, bc = (t & 31) * 4;    // B: 8 k x 32 col-quads
    const int ty = t >> 4, tx = t & 15;

    const float* Ap = g_pooled + (size_t)(rb + alr) * EM + kb + alk;
    const float* Bp = Wb + (size_t)(kb + bk) * HID + cb + bc;

    __shared__ __align__(16) float As[2][8][132];
    __shared__ __align__(16) float Bs[2][8][132];

    float4 pa = *reinterpret_cast<const float4*>(Ap);
    float4 pb = *reinterpret_cast<const float4*>(Bp);
    As[0][alk + 0][alr] = pa.x;
    As[0][alk + 1][alr] = pa.y;
    As[0][alk + 2][alr] = pa.z;
    As[0][alk + 3][alr] = pa.w;
    *reinterpret_cast<float4*>(&Bs[0][bk][bc]) = pb;
    __syncthreads();

    float acc[8][8];
#pragma unroll
    for (int i = 0; i < 8; ++i)
#pragma unroll
        for (int j = 0; j < 8; ++j) acc[i][j] = 0.f;

    for (int kt = 0; kt < NT; ++kt) {
        const int buf = kt & 1;
        if (kt + 1 < NT) {
            pa = *reinterpret_cast<const float4*>(Ap + (kt + 1) * 8);
            pb = *reinterpret_cast<const float4*>(Bp + (size_t)(kt + 1) * 8 * HID);
        }
#pragma unroll
        for (int kk = 0; kk < 8; ++kk) {
            float4 a0 = *reinterpret_cast<const float4*>(&As[buf][kk][ty * 8]);
            float4 a1 = *reinterpret_cast<const float4*>(&As[buf][kk][ty * 8 + 4]);
            float4 b0 = *reinterpret_cast<const float4*>(&Bs[buf][kk][tx * 8]);
            float4 b1 = *reinterpret_cast<const float4*>(&Bs[buf][kk][tx * 8 + 4]);
            float ar[8] = {a0.x, a0.y, a0.z, a0.w, a1.x, a1.y, a1.z, a1.w};
            float br[8] = {b0.x, b0.y, b0.z, b0.w, b1.x, b1.y, b1.z, b1.w};
#pragma unroll
            for (int i = 0; i < 8; ++i)
#pragma unroll
                for (int j = 0; j < 8; ++j) acc[i][j] += ar[i] * br[j];
        }
        if (kt + 1 < NT) {
            const int nb = buf ^ 1;
            As[nb][alk + 0][alr] = pa.x;
            As[nb][alk + 1][alr] = pa.y;
            As[nb][alk + 2][alr] = pa.z;
            As[nb][alk + 3][alr] = pa.w;
            *reinterpret_cast<float4*>(&Bs[nb][bk][bc]) = pb;
            __syncthreads();
        }
    }

    float* C = g_hp + (size_t)z * NF * HID;
#pragma unroll
    for (int i = 0; i < 8; ++i) {
        float* cp = C + (size_t)(rb + ty * 8 + i) * HID + cb + tx * 8;
        *reinterpret_cast<float4*>(cp) =
            make_float4(acc[i][0], acc[i][1], acc[i][2], acc[i][3]);
        *reinterpret_cast<float4*>(cp + 4) =
            make_float4(acc[i][4], acc[i][5], acc[i][6], acc[i][7]);
    }
}

// ---------------- 3b) f2f GEMM (top-64 rows), 64x64 tile, split-K 16 ----------
__global__ __launch_bounds__(256) void gemm_f2f_k() {
    constexpr int KCH = EM / KS_F;               // 160
    constexpr int NT  = KCH / 16;                // 10

    const float* __restrict__ A = g_pooled;
    const float* __restrict__ B = g_pooled;
    float* __restrict__ C = g_fp + (size_t)blockIdx.z * NTOP * NF;

    const int rb = blockIdx.y * 64, cb = blockIdx.x * 64;
    const int kb = blockIdx.z * KCH;
    const int t  = threadIdx.x;
    const int lr = t >> 2, lk = (t & 3) * 4;
    const int ty = t >> 4, tx = t & 15;

    const int arow = g_order[rb + lr];
    const float* Ap = A + (size_t)arow * EM + kb + lk;
    const float* Bp = B + (size_t)(cb + lr) * EM + kb + lk;

    __shared__ __align__(16) float As[2][16][68];
    __shared__ __align__(16) float Bs[2][16][68];

    float4 pa = *reinterpret_cast<const float4*>(Ap);
    float4 pb = *reinterpret_cast<const float4*>(Bp);
    As[0][lk + 0][lr] = pa.x;
    As[0][lk + 1][lr] = pa.y;
    As[0][lk + 2][lr] = pa.z;
    As[0][lk + 3][lr] = pa.w;
    Bs[0][lk + 0][lr] = pb.x;
    Bs[0][lk + 1][lr] = pb.y;
    Bs[0][lk + 2][lr] = pb.z;
    Bs[0][lk + 3][lr] = pb.w;
    __syncthreads();

    float acc[4][4];
#pragma unroll
    for (int i = 0; i < 4; ++i)
#pragma unroll
        for (int j = 0; j < 4; ++j) acc[i][j] = 0.f;

    for (int kt = 0; kt < NT; ++kt) {
        const int buf = kt & 1;
        if (kt + 1 < NT) {
            pa = *reinterpret_cast<const float4*>(Ap + (kt + 1) * 16);
            pb = *reinterpret_cast<const float4*>(Bp + (kt + 1) * 16);
        }
#pragma unroll
        for (int kk = 0; kk < 16; ++kk) {
            float4 av = *reinterpret_cast<const float4*>(&As[buf][kk][ty * 4]);
            float4 bv = *reinterpret_cast<const float4*>(&Bs[buf][kk][tx * 4]);
            float ar[4] = {av.x, av.y, av.z, av.w};
            float br[4] = {bv.x, bv.y, bv.z, bv.w};
#pragma unroll
            for (int i = 0; i < 4; ++i)
#pragma unroll
                for (int j = 0; j < 4; ++j) acc[i][j] += ar[i] * br[j];
        }
        if (kt + 1 < NT) {
            const int nb = buf ^ 1;
            As[nb][lk + 0][lr] = pa.x;
            As[nb][lk + 1][lr] = pa.y;
            As[nb][lk + 2][lr] = pa.z;
            As[nb][lk + 3][lr] = pa.w;
            Bs[nb][lk + 0][lr] = pb.x;
            Bs[nb][lk + 1][lr] = pb.y;
            Bs[nb][lk + 2][lr] = pb.z;
            Bs[nb][lk + 3][lr] = pb.w;
            __syncthreads();
        }
    }

    float rs[4], cs[4];
#pragma unroll
    for (int r = 0; r < 4; ++r) rs[r] = g_invn[g_order[rb + ty * 4 + r]];
#pragma unroll
    for (int j = 0; j < 4; ++j) cs[j] = g_invn[cb + tx * 4 + j];
#pragma unroll
    for (int i = 0; i < 4; ++i) {
        float4 v = make_float4(acc[i][0] * rs[i] * cs[0], acc[i][1] * rs[i] * cs[1],
                               acc[i][2] * rs[i] * cs[2], acc[i][3] * rs[i] * cs[3]);
        *reinterpret_cast<float4*>(C + (size_t)(rb + ty * 4 + i) * 512 + cb + tx * 4) = v;
    }
}

// ---------------- 4) gates: sigmoid(relu(h_sum + tproj) @ W2 + b2) ------------
__global__ __launch_bounds__(128) void gates_k(
    const float* __restrict__ W2, const float* __restrict__ b2) {
    const int n = blockIdx.x, tid = threadIdx.x;   // tid = float4 column
    float4 hv = *(reinterpret_cast<const float4*>(g_tproj) + tid);
#pragma unroll
    for (int s = 0; s < KS_H; ++s) {
        float4 p = *(reinterpret_cast<const float4*>(g_hp + (size_t)s * NF * HID + (size_t)n * HID) + tid);
        hv.x += p.x; hv.y += p.y; hv.z += p.z; hv.w += p.w;
    }
    const float4 w = __ldg(reinterpret_cast<const float4*>(W2) + tid);
    float v = fmaxf(hv.x, 0.f) * w.x + fmaxf(hv.y, 0.f) * w.y
            + fmaxf(hv.z, 0.f) * w.z + fmaxf(hv.w, 0.f) * w.w;
    __shared__ float sm[4];
    int lane = tid & 31, wid = tid >> 5;
#pragma unroll
    for (int o = 16; o > 0; o >>= 1) v += __shfl_down_sync(0xffffffffu, v, o);
    if (lane == 0) sm[wid] = v;
    __syncthreads();
    if (tid == 0) {
        float z = sm[0] + sm[1] + sm[2] + sm[3] + __ldg(b2);
        g_gates[n] = 1.0f / (1.0f + expf(-z));
    }
}

// ---------------- 5) stable descending rank-sort, 16 blocks -------------------
// block b ranks keys [b*32, b*32+32); 16 threads per key, 32 comparisons each.
__global__ __launch_bounds__(NF) void sort_k() {
    __shared__ unsigned long long keys[NF];
    const int t = threadIdx.x;
    unsigned int bits = __float_as_uint(g_gates[t]);  // sigmoid>0 -> monotone bits
    keys[t] = ((unsigned long long)(0xFFFFFFFFu - bits) << 32) | (unsigned int)t;
    __syncthreads();
    const int i = blockIdx.x * 32 + (t >> 4);       // key handled by this group
    const int sub = t & 15;                          // 16-thread group lane
    const unsigned long long me = keys[i];
    int r = 0;
#pragma unroll
    for (int j = 0; j < 32; ++j)
        r += (keys[sub * 32 + j] < me) ? 1 : 0;
#pragma unroll
    for (int o = 8; o > 0; o >>= 1)
        r += __shfl_down_sync(0xffffffffu, r, o, 16);
    if (sub == 0) g_order[r] = i;
}

// ---------------- 6) reduce f2f partials -> similarity bitmask ----------------
__global__ __launch_bounds__(128) void mask_k() {
    const int r = blockIdx.x, t = threadIdx.x;
    float4 s = *(reinterpret_cast<const float4*>(g_fp + (size_t)r * NF) + t);
#pragma unroll
    for (int sp = 1; sp < KS_F; ++sp) {
        float4 p = *(reinterpret_cast<const float4*>(g_fp + (size_t)sp * NTOP * NF + (size_t)r * NF) + t);
        s.x += p.x; s.y += p.y; s.z += p.z; s.w += p.w;
    }
    __shared__ unsigned char nib[128];
    unsigned int n = (s.x > 0.98f ? 1u : 0u) | (s.y > 0.98f ? 2u : 0u)
                   | (s.z > 0.98f ? 4u : 0u) | (s.w > 0.98f ? 8u : 0u);
    nib[t] = (unsigned char)n;
    __syncthreads();
    if (t < 16) {
        unsigned int w = 0;
#pragma unroll
        for (int b = 0; b < 8; ++b) w |= ((unsigned int)nib[8 * t + b]) << (4 * b);
        g_mask[r * 16 + t] = w;
    }
}

// ---------------- 7) greedy selection scan + output ---------------------------
__global__ __launch_bounds__(NF) void scan_k(float* __restrict__ out) {
    __shared__ int s_count, s_done, s_cur, s_take;
    __shared__ unsigned char vis[NF], sel[NF];
    __shared__ unsigned int msk[NTOP * 16];
    const int tid = threadIdx.x;
    vis[tid] = 0;
    sel[tid] = 0;
    if (tid == 0) { s_count = 0; s_done = 0; }
    msk[tid] = g_mask[tid];
    msk[tid + 512] = g_mask[tid + 512];
    __syncthreads();
    for (int pos = 0; pos < NF; ++pos) {
        if (tid == 0) {
            if (s_count >= 32) {
                s_done = 1;
            } else {
                int cur = g_order[pos];
                s_cur = cur;
                int take = vis[cur] ? 0 : 1;
                s_take = take;
                if (take) { sel[cur] = 1; s_count++; }
            }
        }
        __syncthreads();
        if (s_done) break;
        if (s_take) {
            bool hit;
            if (pos < NTOP) {
                hit = (msk[pos * 16 + (tid >> 5)] >> (tid & 31)) & 1u;
            } else {                               // exact fallback (not hit on normal data)
                const float* a = g_pooled + (size_t)s_cur * EM;
                const float* bb = g_pooled + (size_t)tid * EM;
                float d = 0.f;
                for (int e = 0; e < EM; ++e) d += a[e] * bb[e];
                hit = d * g_invn[s_cur] * g_invn[tid] > 0.98f;
            }
            if (hit) vis[tid] = 1;
        }
        __syncthreads();
    }
    __syncthreads();
    out[tid] = (float)sel[tid];
    out[NF + tid] = g_gates[tid];
}

// ---------------- launch ------------------------------------------------------
extern "C" void kernel_launch(void* const* d_in, const int* in_sizes, int n_in,
                              void* d_out, int out_size) {
    const float* img    = (const float*)d_in[0];
    const float* txt    = (const float*)d_in[1];
    const float* ln_t_g = (const float*)d_in[2];
    const float* ln_t_b = (const float*)d_in[3];
    const float* ln_l_g = (const float*)d_in[4];
    const float* ln_l_b = (const float*)d_in[5];
    const float* W1     = (const float*)d_in[6];
    const float* b1     = (const float*)d_in[7];
    const float* W2     = (const float*)d_in[8];
    const float* b2     = (const float*)d_in[9];
    float* out = (float*)d_out;

    pool_tproj_k<<<NF + 16, POOL_T>>>(img, ln_l_g, ln_l_b,
                                      txt, ln_t_g, ln_t_b, W1, b1);
    gemm_h_k<<<dim3(4, 4, KS_H), 256>>>(W1 + (size_t)EM * HID);
    gates_k<<<NF, 128>>>(W2, b2);
    sort_k<<<16, NF>>>();
    gemm_f2f_k<<<dim3(8, 1, KS_F), 256>>>();
    mask_k<<<NTOP, 128>>>();
    scan_k<<<1, NF>>>(out);
}